// round 10
// baseline (speedup 1.0000x reference)
#include <cuda_runtime.h>
#include <cuda_bf16.h>
#include <cuda_fp16.h>
#include <cstdint>

#define EPSF 1e-5f
#define HW   16384
#define CHW  2097152

// ---------------- scratch (static device memory) ----------------
__device__ float g_wcf[5*16384];                        // composed 1x1 weights fp32
__device__ float g_bcf[5*128];                          // composed biases
__device__ __align__(16) unsigned short g_wsh[5*2*128*64];   // fp16 [which][pn][o][ci64]
__device__ __align__(16) unsigned short g_tih[3ull*8*CHW];   // fp16 inputs T: [inp][b][h][w][c]
__device__ __align__(16) unsigned short g_x1h[8*CHW];        // fp16 [b][h][c][w]
__device__ __align__(16) unsigned short g_x2h[8*CHW];
__device__ __align__(16) unsigned short g_xfh[8*CHW];
__device__ __align__(16) unsigned short g_xrh[8*CHW];
__device__ __align__(16) unsigned short g_xph[8*CHW];        // fp16 [b][h][w][d]
__device__ unsigned short g_wh[9*6*384*64];             // conv3x3 W fp16: [tap][chunk][o][ci]
__device__ unsigned short g_bhi[8ull*130*130*384];      // conv3x3 in fp16: [b][hp][wp][ci]

// ---------------- helpers ----------------
__device__ __forceinline__ uint32_t smem_u32(const void* p){
    uint32_t a; asm("{ .reg .u64 t; cvta.to.shared.u64 t, %1; cvt.u32.u64 %0, t; }"
                    : "=r"(a) : "l"(p)); return a;
}
#define SWZ(x) ((x) ^ (((x)>>3)&0x70))
#define CP16(dst, src) asm volatile("cp.async.cg.shared.global [%0], [%1], 16;" \
    :: "r"((uint32_t)(dst)), "l"((const void*)(src)) : "memory")
#define CP_COMMIT() asm volatile("cp.async.commit_group;" ::: "memory")
#define CP_WAIT0()  asm volatile("cp.async.wait_group 0;" ::: "memory")
#define CP_WAIT1()  asm volatile("cp.async.wait_group 1;" ::: "memory")
#define LDSM4(r0,r1,r2,r3,a) asm volatile( \
    "ldmatrix.sync.aligned.m8n8.x4.shared.b16 {%0,%1,%2,%3}, [%4];" \
    : "=r"(r0),"=r"(r1),"=r"(r2),"=r"(r3) : "r"(a))
#define MMAF16(c,a,b) asm volatile( \
    "mma.sync.aligned.m16n8k16.row.col.f32.f16.f16.f32 " \
    "{%0,%1,%2,%3},{%4,%5,%6,%7},{%8,%9},{%0,%1,%2,%3};" \
    : "+f"((c)[0]),"+f"((c)[1]),"+f"((c)[2]),"+f"((c)[3]) \
    : "r"((a)[0]),"r"((a)[1]),"r"((a)[2]),"r"((a)[3]), "r"((b)[0]),"r"((b)[1]))

__device__ __forceinline__ unsigned pack_f16(float v0, float v1){
    unsigned hp; asm("cvt.rn.f16x2.f32 %0, %1, %2;" : "=r"(hp) : "f"(v1), "f"(v0));
    return hp;
}

// 128x128x64 GEMM chunk, single-pass fp16. a0/b0 = byte offsets of panels in smem.
__device__ __forceinline__ void gemm64f(uint32_t sb, uint32_t a0, uint32_t b0,
                                        int l, int mw, int nw, float acc[4][4][4])
{
#pragma unroll
    for (int ks = 0; ks < 4; ks++){
        uint32_t ah[4][4], bh[4][2];
        const uint32_t abyte = ks*32 + ((l>>4)<<4);
#pragma unroll
        for (int f = 0; f < 4; f++){
            int row = mw*64 + f*16 + (l & 15);
            uint32_t off = SWZ((uint32_t)(row*128) + abyte);
            LDSM4(ah[f][0],ah[f][1],ah[f][2],ah[f][3], sb + a0 + off);
        }
        const uint32_t bbyte = ks*32 + (((l>>3)&1)<<4);
#pragma unroll
        for (int g2 = 0; g2 < 2; g2++){
            int rowb = nw*32 + g2*16 + (l & 7) + ((l>>4)<<3);
            uint32_t off = SWZ((uint32_t)(rowb*128) + bbyte);
            uint32_t t0,t1,t2,t3;
            LDSM4(t0,t1,t2,t3, sb + b0 + off);
            bh[g2*2][0]=t0; bh[g2*2][1]=t1; bh[g2*2+1][0]=t2; bh[g2*2+1][1]=t3;
        }
#pragma unroll
        for (int f = 0; f < 4; f++)
#pragma unroll
            for (int g = 0; g < 4; g++)
                MMAF16(acc[f][g], ah[f], bh[g]);
    }
}

__device__ __forceinline__ void block_reduce_2(float& s, float& q, float* red)
{
#pragma unroll
    for (int off=16; off>0; off>>=1){
        s += __shfl_down_sync(0xffffffffu, s, off);
        q += __shfl_down_sync(0xffffffffu, q, off);
    }
    const int wid = threadIdx.x >> 5;
    if ((threadIdx.x & 31) == 0){ red[wid] = s; red[8+wid] = q; }
    __syncthreads();
    s = 0.f; q = 0.f;
#pragma unroll
    for (int i=0;i<8;i++){ s += red[i]; q += red[8+i]; }
    __syncthreads();
}

// ============ transpose+convert inputs: [b][c][h][w] -> [inp][b][h][w][c] fp16 =====
__global__ __launch_bounds__(256) void xpose_cvt(const float* __restrict__ x,
    const float* __restrict__ xf, const float* __restrict__ xr)
{
    extern __shared__ float tl[];   // [128][133]
    const int inp = blockIdx.x, h = blockIdx.y, b = blockIdx.z;
    const float* src = inp==0 ? x : (inp==1 ? xf : xr);
    const int tid = threadIdx.x;
    const float* sp = src + (size_t)b*CHW + (size_t)h*128;
    for (int u = tid; u < 4096; u += 256){
        int c = u >> 5, q = u & 31;
        float4 v = *(const float4*)(sp + (size_t)c*HW + 4*q);
        float* d = tl + c*133 + 4*q;
        d[0]=v.x; d[1]=v.y; d[2]=v.z; d[3]=v.w;
    }
    __syncthreads();
    const size_t obase = ((size_t)inp*1024 + b*128 + h) * 16384;
    for (int u = tid; u < 4096; u += 256){
        int cg = u & 31, w = u >> 5;
        float v0 = tl[(4*cg+0)*133 + w], v1 = tl[(4*cg+1)*133 + w];
        float v2 = tl[(4*cg+2)*133 + w], v3 = tl[(4*cg+3)*133 + w];
        unsigned hp0 = pack_f16(v0, v1);
        unsigned hp1 = pack_f16(v2, v3);
        *(uint2*)&g_tih[obase + (size_t)w*128 + 4*cg] = make_uint2(hp0, hp1);
    }
}

// ============ compose 1x1 weights: which 0:Wx 1:W1@Wx 2:W2@Wx 3:Wf 4:Wr =====
__global__ __launch_bounds__(256) void wcompose_kernel(
    const float* __restrict__ Wx, const float* __restrict__ bx,
    const float* __restrict__ W1, const float* __restrict__ b1,
    const float* __restrict__ W2, const float* __restrict__ b2,
    const float* __restrict__ Wf, const float* __restrict__ bf,
    const float* __restrict__ Wr, const float* __restrict__ br_)
{
    extern __shared__ float S[];
    const int which = blockIdx.x, tid = threadIdx.x;
    if (which == 0 || which >= 3){
        const float* Ws = which==0 ? Wx : (which==3 ? Wf : Wr);
        const float* bs = which==0 ? bx : (which==3 ? bf : br_);
        for (int i = tid; i < 16384; i += 256) g_wcf[which*16384 + i] = Ws[i];
        if (tid < 128) g_bcf[which*128 + tid] = bs[tid];
        return;
    }
    const float* Wo = (which==1) ? W1 : W2;
    const float* bo = (which==1) ? b1 : b2;
    for (int i = tid; i < 16384; i += 256) S[i] = Wx[i];
    __syncthreads();
    int r = tid >> 1, c0 = (tid & 1) * 64;
    float acc[64];
#pragma unroll
    for (int j = 0; j < 64; j++) acc[j] = 0.f;
    for (int k = 0; k < 128; k++){
        float a = Wo[r*128 + k];
#pragma unroll
        for (int j = 0; j < 64; j++) acc[j] = fmaf(a, S[k*128 + c0 + j], acc[j]);
    }
    for (int j = 0; j < 64; j++) g_wcf[which*16384 + r*128 + c0 + j] = acc[j];
    if (tid < 128){
        float s = bo[tid];
        for (int k = 0; k < 128; k++) s = fmaf(Wo[tid*128 + k], bx[k], s);
        g_bcf[which*128 + tid] = s;
    }
}

// split composed weights to fp16 panels [which][pn][o][ci64]
__global__ void wsplit_kernel()
{
    int idx = blockIdx.x*256 + threadIdx.x;
    if (idx >= 81920) return;
    int ci = idx & 63, o = (idx >> 6) & 127, pn = (idx >> 13) & 1, which = idx >> 14;
    g_wsh[idx] = __half_as_ushort(__float2half(g_wcf[which*16384 + o*128 + pn*64 + ci]));
}

// ============ conv1x1: single-pass fp16, 64KB smem, double-buffered =========
__global__ __launch_bounds__(256, 2) void conv1x1_mma(void)
{
    extern __shared__ char dsm[];
    const int tid = threadIdx.x, l = tid & 31, wid = tid >> 5;
    const int mw = wid & 1, nw = wid >> 1;
    const int which = blockIdx.x, h = blockIdx.y, b = blockIdx.z;
    const uint32_t sb = smem_u32(dsm);
    const int inp = (which < 3) ? 0 : which - 2;

    const char* wH = (const char*)g_wsh + which*32768;
    const size_t slab = ((size_t)inp*1024 + b*128 + h)*32768;
    const char* tH = (const char*)g_tih + slab;

    auto stage = [&](int pn){
        uint32_t base = pn*32768;
        for (int u = tid; u < 1024; u += 256){
            CP16(sb + base + SWZ((uint32_t)(u*16)), wH + pn*16384 + u*16);
            int w = u >> 3, j = u & 7;
            CP16(sb + base + 16384 + SWZ((uint32_t)(w*128 + j*16)), tH + w*256 + pn*128 + j*16);
        }
    };

    float acc[4][4][4];
#pragma unroll
    for (int f=0;f<4;f++)
#pragma unroll
        for (int g=0;g<4;g++)
#pragma unroll
            for (int e=0;e<4;e++) acc[f][g][e] = 0.f;

    stage(0); CP_COMMIT();
    stage(1); CP_COMMIT();
    CP_WAIT1(); __syncthreads();
    gemm64f(sb, 0, 16384, l, mw, nw, acc);
    CP_WAIT0(); __syncthreads();
    gemm64f(sb, 32768, 49152, l, mw, nw, acc);

    const size_t base = (size_t)(b*128 + h)*16384;
    if (which == 0){
        __syncthreads();
        unsigned short* tile = (unsigned short*)dsm;
#pragma unroll
        for (int f = 0; f < 4; f++){
            int r1 = mw*64 + f*16 + (l>>2), r2 = r1 + 8;
            float b1v = g_bcf[r1], b2v = g_bcf[r2];
#pragma unroll
            for (int g = 0; g < 4; g++){
                int w = nw*32 + g*8 + 2*(l & 3);
                tile[(size_t)w*128 + r1]     = __half_as_ushort(__float2half(acc[f][g][0] + b1v));
                tile[(size_t)(w+1)*128 + r1] = __half_as_ushort(__float2half(acc[f][g][1] + b1v));
                tile[(size_t)w*128 + r2]     = __half_as_ushort(__float2half(acc[f][g][2] + b2v));
                tile[(size_t)(w+1)*128 + r2] = __half_as_ushort(__float2half(acc[f][g][3] + b2v));
            }
        }
        __syncthreads();
        for (int u = tid; u < 2048; u += 256){
            *(uint4*)((char*)(g_xph + base) + u*16) = *(uint4*)(dsm + u*16);
        }
    } else {
        unsigned short* oh;
        if (which == 1) oh = g_x1h;
        else if (which == 2) oh = g_x2h;
        else if (which == 3) oh = g_xfh;
        else oh = g_xrh;
#pragma unroll
        for (int f = 0; f < 4; f++){
            int r1 = mw*64 + f*16 + (l>>2), r2 = r1 + 8;
            float b1v = g_bcf[which*128 + r1], b2v = g_bcf[which*128 + r2];
#pragma unroll
            for (int g = 0; g < 4; g++){
                int w = nw*32 + g*8 + 2*(l & 3);
                *(unsigned*)&oh[base + (size_t)r1*128 + w] = pack_f16(acc[f][g][0] + b1v, acc[f][g][1] + b1v);
                *(unsigned*)&oh[base + (size_t)r2*128 + w] = pack_f16(acc[f][g][2] + b2v, acc[f][g][3] + b2v);
            }
        }
    }
}

// ============ attention: single-pass fp16, 64KB smem ========================
__global__ __launch_bounds__(256, 2) void attn_mma(void)
{
    extern __shared__ char dsm[];
    __shared__ float red[16];
    const int tid = threadIdx.x, l = tid & 31, wid = tid >> 5;
    const int mw = wid & 1, nw = wid >> 1;
    const int br = blockIdx.x, h = blockIdx.y, b = blockIdx.z;
    const uint32_t sb = smem_u32(dsm);
    const size_t slab = (size_t)(b*128 + h) * 32768;
    const char* aH = (const char*)(br ? g_x2h : g_x1h) + slab;
    const char* bH = (const char*)(br ? g_xrh : g_xfh) + slab;
    const char* pH = (const char*)g_xph + slab;

    for (int u = tid; u < 2048; u += 256){
        int c = u >> 4, j = u & 15;
        int pn = j >> 3, jj = j & 7;
        uint32_t d = pn*16384 + SWZ((uint32_t)(c*128 + jj*16));
        CP16(sb + d,         aH + c*256 + pn*128 + jj*16);
        CP16(sb + 32768 + d, bH + c*256 + pn*128 + jj*16);
    }
    CP_COMMIT(); CP_WAIT0(); __syncthreads();

    float acc[4][4][4];
#pragma unroll
    for (int f=0;f<4;f++)
#pragma unroll
        for (int g=0;g<4;g++)
#pragma unroll
            for (int e=0;e<4;e++) acc[f][g][e] = 0.f;
    gemm64f(sb, 0,     32768, l, mw, nw, acc);
    gemm64f(sb, 16384, 49152, l, mw, nw, acc);

    float ls = 0.f, lq = 0.f;
#pragma unroll
    for (int f=0;f<4;f++)
#pragma unroll
        for (int g=0;g<4;g++)
#pragma unroll
            for (int e=0;e<4;e++){ ls += acc[f][g][e]; lq += acc[f][g][e]*acc[f][g][e]; }
    block_reduce_2(ls, lq, red);
    float mean = ls * (1.f/16384.f);
    float inv  = rsqrtf(lq * (1.f/16384.f) - mean*mean + EPSF);

    for (int u = tid; u < 2048; u += 256){
        int w = u >> 4, j = u & 15;
        int pn = j >> 3, jj = j & 7;
        CP16(sb + 32768 + pn*16384 + SWZ((uint32_t)(w*128 + jj*16)),
             pH + w*256 + pn*128 + jj*16);
    }
    CP_COMMIT();

#pragma unroll
    for (int f = 0; f < 4; f++){
        int c1 = mw*64 + f*16 + (l>>2), c2 = c1 + 8;
#pragma unroll
        for (int g = 0; g < 4; g++){
            int dd = nw*32 + g*8 + 2*(l & 3);
            uint32_t pn = (uint32_t)(dd >> 6)*16384;
            uint32_t byt = (uint32_t)((dd & 63)*2);
            *(unsigned*)(dsm + pn + SWZ((uint32_t)(c1*128) + byt)) =
                pack_f16((acc[f][g][0]-mean)*inv, (acc[f][g][1]-mean)*inv);
            *(unsigned*)(dsm + pn + SWZ((uint32_t)(c2*128) + byt)) =
                pack_f16((acc[f][g][2]-mean)*inv, (acc[f][g][3]-mean)*inv);
        }
    }
    CP_WAIT0(); __syncthreads();

#pragma unroll
    for (int f=0;f<4;f++)
#pragma unroll
        for (int g=0;g<4;g++)
#pragma unroll
            for (int e=0;e<4;e++) acc[f][g][e] = 0.f;
    gemm64f(sb, 0,     32768, l, mw, nw, acc);
    gemm64f(sb, 16384, 49152, l, mw, nw, acc);

    ls = 0.f; lq = 0.f;
#pragma unroll
    for (int f=0;f<4;f++)
#pragma unroll
        for (int g=0;g<4;g++)
#pragma unroll
            for (int e=0;e<4;e++){ ls += acc[f][g][e]; lq += acc[f][g][e]*acc[f][g][e]; }
    block_reduce_2(ls, lq, red);
    mean = ls * (1.f/16384.f);
    inv  = rsqrtf(lq * (1.f/16384.f) - mean*mean + EPSF);

    unsigned short* tile = (unsigned short*)dsm;
#pragma unroll
    for (int f = 0; f < 4; f++){
        int c1 = mw*64 + f*16 + (l>>2), c2 = c1 + 8;
#pragma unroll
        for (int g = 0; g < 4; g++){
            int w = nw*32 + g*8 + 2*(l & 3);
            tile[(size_t)w*128 + c1]     = __half_as_ushort(__float2half((acc[f][g][0]-mean)*inv));
            tile[(size_t)(w+1)*128 + c1] = __half_as_ushort(__float2half((acc[f][g][1]-mean)*inv));
            tile[(size_t)w*128 + c2]     = __half_as_ushort(__float2half((acc[f][g][2]-mean)*inv));
            tile[(size_t)(w+1)*128 + c2] = __half_as_ushort(__float2half((acc[f][g][3]-mean)*inv));
        }
    }
    __syncthreads();
    const size_t rowb = (((size_t)b*130 + (h+1))*130 + 1)*384 + br*128;
    for (int u = tid; u < 2048; u += 256){
        int w = u >> 4, j = u & 15;
        uint4 v = *(uint4*)(dsm + w*256 + j*16);
        *(uint4*)((char*)g_bhi + (rowb + (size_t)w*384)*2 + j*16) = v;
    }
}

// ============ conv3x3 weight prep: fp16 [tap][chunk][o][ci] =================
__global__ void presplit_kernel(const float* __restrict__ Wm)
{
    int idx = blockIdx.x*256 + threadIdx.x;
    if (idx >= 9*6*384*64) return;
    int ci = idx & 63;
    int o  = (idx >> 6) % 384;
    int r  = idx >> 6; r /= 384;
    int chunk = r % 6, tap = r / 6;
    float v = Wm[(size_t)o*3456 + (chunk*64 + ci)*9 + tap];
    g_wh[idx] = __half_as_ushort(__float2half(v));
}

// ===== conv3x3 input (x third only) to channels-last fp16 ===================
__global__ __launch_bounds__(256) void padcvt_kernel(const float* __restrict__ x)
{
    __shared__ float tile[64*129];
    const int c0 = 256 + (blockIdx.x << 6), h = blockIdx.y, b = blockIdx.z;
    const int tid = threadIdx.x;
    for (int idx = tid; idx < 64*128; idx += 256){
        int ci = idx >> 7, w = idx & 127;
        tile[ci*129 + w] = x[((size_t)b*128 + (c0-256+ci))*HW + h*128 + w];
    }
    __syncthreads();
    const size_t obase = (((size_t)b*130 + (h+1))*130)*384;
    for (int idx = tid; idx < 128*8; idx += 256){
        int w = idx >> 3, u = idx & 7;
        unsigned Hp[4];
#pragma unroll
        for (int e2 = 0; e2 < 4; e2++){
            float v0 = tile[(u*8 + 2*e2    )*129 + w];
            float v1 = tile[(u*8 + 2*e2 + 1)*129 + w];
            Hp[e2] = pack_f16(v0, v1);
        }
        size_t off2 = (obase + (size_t)(w+1)*384 + c0 + u*8) * 2;
        *(uint4*)((char*)g_bhi + off2) = make_uint4(Hp[0],Hp[1],Hp[2],Hp[3]);
    }
}

// ======= conv3x3 fp16, TWO output rows per CTA (M=128, N=256) ===============
// stage: A 16KB | B0 16.64KB (row h0+kh) | B1 16.64KB (row h0+1+kh)
#define OFF3_A  0
#define OFF3_B0 16384
#define OFF3_B1 33024
#define STAGE3  49664

__global__ __launch_bounds__(256, 1) void conv3x3_tc(
    const float* __restrict__ bm, const float* __restrict__ gamma,
    const float* __restrict__ beta, const float* __restrict__ rmean,
    const float* __restrict__ rvar, float* __restrict__ out)
{
    extern __shared__ char dsm[];
    const int tid = threadIdx.x, l = tid & 31, wid = tid >> 5;
    const int mw = wid & 1, nw = wid >> 1;
    const int h0 = blockIdx.y << 1, o0 = blockIdx.x << 7, b = blockIdx.z;
    const uint32_t sb = smem_u32(dsm);

    float acc0[4][4][4], acc1[4][4][4];
#pragma unroll
    for (int f=0;f<4;f++)
#pragma unroll
        for (int g=0;g<4;g++)
#pragma unroll
            for (int e=0;e<4;e++){ acc0[f][g][e] = 0.f; acc1[f][g][e] = 0.f; }

    auto stage = [&](int it, int st){
        int tap = it/6, chunk = it - tap*6;
        int kh = tap/3;
        uint32_t s0 = sb + st*STAGE3;
        const char* srcA = (const char*)g_wh + (((size_t)tap*6 + chunk)*384 + o0)*128;
        for (int u = tid; u < 1024; u += 256){
            CP16(s0 + OFF3_A + SWZ(u*16), srcA + u*16);
        }
        size_t row0 = ((size_t)b*130 + (h0+kh))*130*768 + (size_t)chunk*128;
        const char* BH = (const char*)g_bhi;
        for (int u = tid; u < 1040; u += 256){
            int wp = u >> 3, j = u & 7;
            uint32_t d = SWZ(wp*128 + j*16);
            size_t so = row0 + (size_t)wp*768 + j*16;
            CP16(s0 + OFF3_B0 + d, BH + so);
            CP16(s0 + OFF3_B1 + d, BH + so + 130*768);
        }
    };

    stage(0, 0); CP_COMMIT(); CP_WAIT0(); __syncthreads();

    for (int it = 0; it < 54; it++){
        const int p = it & 1;
        if (it + 1 < 54){ stage(it+1, 1-p); CP_COMMIT(); }

        const int kw = (it/6) % 3;
        const uint32_t s0 = sb + p*STAGE3;
#pragma unroll
        for (int ks = 0; ks < 4; ks++){
            uint32_t ah[4][4], bh[4][2];
            const uint32_t abyte = ks*32 + ((l>>4)<<4);
#pragma unroll
            for (int f = 0; f < 4; f++){
                int row = mw*64 + f*16 + (l & 15);
                uint32_t off = SWZ((uint32_t)(row*128) + abyte);
                LDSM4(ah[f][0],ah[f][1],ah[f][2],ah[f][3], s0 + OFF3_A + off);
            }
            const uint32_t bbyte = ks*32 + (((l>>3)&1)<<4);
            const int rb0 = nw*32 + kw + (l & 7) + ((l>>4)<<3);
            // ---- row h0 (B0 panel) ----
#pragma unroll
            for (int g2 = 0; g2 < 2; g2++){
                uint32_t off = SWZ((uint32_t)((rb0 + g2*16)*128) + bbyte);
                uint32_t t0,t1,t2,t3;
                LDSM4(t0,t1,t2,t3, s0 + OFF3_B0 + off);
                bh[g2*2][0]=t0; bh[g2*2][1]=t1; bh[g2*2+1][0]=t2; bh[g2*2+1][1]=t3;
            }
#pragma unroll
            for (int f = 0; f < 4; f++)
#pragma unroll
                for (int g = 0; g < 4; g++)
                    MMAF16(acc0[f][g], ah[f], bh[g]);
            // ---- row h0+1 (B1 panel) ----
#pragma unroll
            for (int g2 = 0; g2 < 2; g2++){
                uint32_t off = SWZ((uint32_t)((rb0 + g2*16)*128) + bbyte);
                uint32_t t0,t1,t2,t3;
                LDSM4(t0,t1,t2,t3, s0 + OFF3_B1 + off);
                bh[g2*2][0]=t0; bh[g2*2][1]=t1; bh[g2*2+1][0]=t2; bh[g2*2+1][1]=t3;
            }
#pragma unroll
            for (int f = 0; f < 4; f++)
#pragma unroll
                for (int g = 0; g < 4; g++)
                    MMAF16(acc1[f][g], ah[f], bh[g]);
        }
        CP_WAIT0();
        __syncthreads();
    }

#pragma unroll
    for (int f = 0; f < 4; f++){
        int o1 = o0 + mw*64 + f*16 + (l >> 2);
        int o2 = o1 + 8;
        float sc1 = gamma[o1] * rsqrtf(rvar[o1] + EPSF);
        float sh1 = beta[o1] + (bm[o1] - rmean[o1]) * sc1;
        float sc2 = gamma[o2] * rsqrtf(rvar[o2] + EPSF);
        float sh2 = beta[o2] + (bm[o2] - rmean[o2]) * sc2;
        float* r1 = out + ((size_t)(b*384 + o1))*HW + (size_t)h0*128;
        float* r2 = out + ((size_t)(b*384 + o2))*HW + (size_t)h0*128;
#pragma unroll
        for (int g = 0; g < 4; g++){
            int w = nw*32 + g*8 + 2*(l & 3);
            float2 v;
            v.x = fmaxf(fmaf(acc0[f][g][0], sc1, sh1), 0.f);
            v.y = fmaxf(fmaf(acc0[f][g][1], sc1, sh1), 0.f);
            *(float2*)(r1 + w) = v;
            v.x = fmaxf(fmaf(acc0[f][g][2], sc2, sh2), 0.f);
            v.y = fmaxf(fmaf(acc0[f][g][3], sc2, sh2), 0.f);
            *(float2*)(r2 + w) = v;
            v.x = fmaxf(fmaf(acc1[f][g][0], sc1, sh1), 0.f);
            v.y = fmaxf(fmaf(acc1[f][g][1], sc1, sh1), 0.f);
            *(float2*)(r1 + 128 + w) = v;
            v.x = fmaxf(fmaf(acc1[f][g][2], sc2, sh2), 0.f);
            v.y = fmaxf(fmaf(acc1[f][g][3], sc2, sh2), 0.f);
            *(float2*)(r2 + 128 + w) = v;
        }
    }
}

// =============================================================================
extern "C" void kernel_launch(void* const* d_in, const int* in_sizes, int n_in,
                              void* d_out, int out_size)
{
    const float* x  = (const float*)d_in[0];
    const float* xf = (const float*)d_in[1];
    const float* xr = (const float*)d_in[2];
    const float* Wx = (const float*)d_in[3];
    const float* bx = (const float*)d_in[4];
    const float* W1 = (const float*)d_in[5];
    const float* b1 = (const float*)d_in[6];
    const float* W2 = (const float*)d_in[7];
    const float* b2 = (const float*)d_in[8];
    const float* Wf = (const float*)d_in[9];
    const float* bf = (const float*)d_in[10];
    const float* Wr = (const float*)d_in[11];
    const float* br_ = (const float*)d_in[12];
    const float* Wm = (const float*)d_in[13];
    const float* bm = (const float*)d_in[14];
    const float* gamma = (const float*)d_in[15];
    const float* beta  = (const float*)d_in[16];
    const float* rmean = (const float*)d_in[17];
    const float* rvar  = (const float*)d_in[18];
    float* out = (float*)d_out;

    cudaFuncSetAttribute(xpose_cvt,   cudaFuncAttributeMaxDynamicSharedMemorySize, 68096);
    cudaFuncSetAttribute(wcompose_kernel, cudaFuncAttributeMaxDynamicSharedMemorySize, 65536);
    cudaFuncSetAttribute(conv1x1_mma, cudaFuncAttributeMaxDynamicSharedMemorySize, 65536);
    cudaFuncSetAttribute(attn_mma,    cudaFuncAttributeMaxDynamicSharedMemorySize, 65536);
    cudaFuncSetAttribute(conv3x3_tc,  cudaFuncAttributeMaxDynamicSharedMemorySize, 2*STAGE3);

    xpose_cvt<<<dim3(3, 128, 8), 256, 68096>>>(x, xf, xr);
    wcompose_kernel<<<5, 256, 65536>>>(Wx, bx, W1, b1, W2, b2, Wf, bf, Wr, br_);
    wsplit_kernel<<<320, 256>>>();
    conv1x1_mma<<<dim3(5, 128, 8), 256, 65536>>>();
    attn_mma<<<dim3(2, 128, 8), 256, 65536>>>();
    presplit_kernel<<<5184, 256>>>(Wm);
    padcvt_kernel<<<dim3(2, 128, 8), 256>>>(x);
    conv3x3_tc<<<dim3(3, 64, 8), 256, 2*STAGE3>>>(bm, gamma, beta, rmean, rvar, out);
}

// round 11
// speedup vs baseline: 1.0593x; 1.0593x over previous
#include <cuda_runtime.h>
#include <cuda_bf16.h>
#include <cuda_fp16.h>
#include <cstdint>

#define EPSF 1e-5f
#define HW   16384
#define CHW  2097152

// ---------------- scratch (static device memory) ----------------
__device__ float g_wcf[5*16384];                        // composed 1x1 weights fp32
__device__ float g_bcf[5*128];                          // composed biases
__device__ __align__(16) unsigned short g_wsh[5*2*128*64];   // fp16 [which][pn][o][ci64]
__device__ __align__(16) unsigned short g_tih[3ull*8*CHW];   // fp16 inputs T: [inp][b][h][w][c]
__device__ __align__(16) unsigned short g_x1h[8*CHW];        // fp16 [b][h][c][w]
__device__ __align__(16) unsigned short g_x2h[8*CHW];
__device__ __align__(16) unsigned short g_xfh[8*CHW];
__device__ __align__(16) unsigned short g_xrh[8*CHW];
__device__ __align__(16) unsigned short g_xph[8*CHW];        // fp16 [b][h][w][d]
__device__ unsigned short g_wh[9*6*384*64];             // conv3x3 W fp16: [tap][chunk][o][ci]
__device__ unsigned short g_bhi[8ull*130*130*384];      // conv3x3 in fp16: [b][hp][wp][ci]

// ---------------- helpers ----------------
__device__ __forceinline__ uint32_t smem_u32(const void* p){
    uint32_t a; asm("{ .reg .u64 t; cvta.to.shared.u64 t, %1; cvt.u32.u64 %0, t; }"
                    : "=r"(a) : "l"(p)); return a;
}
#define SWZ(x) ((x) ^ (((x)>>3)&0x70))
#define CP16(dst, src) asm volatile("cp.async.cg.shared.global [%0], [%1], 16;" \
    :: "r"((uint32_t)(dst)), "l"((const void*)(src)) : "memory")
#define CP_COMMIT() asm volatile("cp.async.commit_group;" ::: "memory")
#define CP_WAIT0()  asm volatile("cp.async.wait_group 0;" ::: "memory")
#define CP_WAIT1()  asm volatile("cp.async.wait_group 1;" ::: "memory")
#define LDSM4(r0,r1,r2,r3,a) asm volatile( \
    "ldmatrix.sync.aligned.m8n8.x4.shared.b16 {%0,%1,%2,%3}, [%4];" \
    : "=r"(r0),"=r"(r1),"=r"(r2),"=r"(r3) : "r"(a))
#define MMAF16(c,a,b) asm volatile( \
    "mma.sync.aligned.m16n8k16.row.col.f32.f16.f16.f32 " \
    "{%0,%1,%2,%3},{%4,%5,%6,%7},{%8,%9},{%0,%1,%2,%3};" \
    : "+f"((c)[0]),"+f"((c)[1]),"+f"((c)[2]),"+f"((c)[3]) \
    : "r"((a)[0]),"r"((a)[1]),"r"((a)[2]),"r"((a)[3]), "r"((b)[0]),"r"((b)[1]))

__device__ __forceinline__ unsigned pack_f16(float v0, float v1){
    unsigned hp; asm("cvt.rn.f16x2.f32 %0, %1, %2;" : "=r"(hp) : "f"(v1), "f"(v0));
    return hp;
}

// 128x128x64 GEMM chunk, single-pass fp16. a0/b0 = byte offsets of panels in smem.
__device__ __forceinline__ void gemm64f(uint32_t sb, uint32_t a0, uint32_t b0,
                                        int l, int mw, int nw, float acc[4][4][4])
{
#pragma unroll
    for (int ks = 0; ks < 4; ks++){
        uint32_t ah[4][4], bh[4][2];
        const uint32_t abyte = ks*32 + ((l>>4)<<4);
#pragma unroll
        for (int f = 0; f < 4; f++){
            int row = mw*64 + f*16 + (l & 15);
            uint32_t off = SWZ((uint32_t)(row*128) + abyte);
            LDSM4(ah[f][0],ah[f][1],ah[f][2],ah[f][3], sb + a0 + off);
        }
        const uint32_t bbyte = ks*32 + (((l>>3)&1)<<4);
#pragma unroll
        for (int g2 = 0; g2 < 2; g2++){
            int rowb = nw*32 + g2*16 + (l & 7) + ((l>>4)<<3);
            uint32_t off = SWZ((uint32_t)(rowb*128) + bbyte);
            uint32_t t0,t1,t2,t3;
            LDSM4(t0,t1,t2,t3, sb + b0 + off);
            bh[g2*2][0]=t0; bh[g2*2][1]=t1; bh[g2*2+1][0]=t2; bh[g2*2+1][1]=t3;
        }
#pragma unroll
        for (int f = 0; f < 4; f++)
#pragma unroll
            for (int g = 0; g < 4; g++)
                MMAF16(acc[f][g], ah[f], bh[g]);
    }
}

__device__ __forceinline__ void block_reduce_2(float& s, float& q, float* red)
{
#pragma unroll
    for (int off=16; off>0; off>>=1){
        s += __shfl_down_sync(0xffffffffu, s, off);
        q += __shfl_down_sync(0xffffffffu, q, off);
    }
    const int wid = threadIdx.x >> 5;
    if ((threadIdx.x & 31) == 0){ red[wid] = s; red[8+wid] = q; }
    __syncthreads();
    s = 0.f; q = 0.f;
#pragma unroll
    for (int i=0;i<8;i++){ s += red[i]; q += red[8+i]; }
    __syncthreads();
}

// ==== transpose+convert: [b][c][h][w] -> [inp][b][h][w][c] fp16; inp0 also -> g_bhi ====
__global__ __launch_bounds__(256) void xpose_cvt(const float* __restrict__ x,
    const float* __restrict__ xf, const float* __restrict__ xr)
{
    extern __shared__ float tl[];   // [128][133]
    const int inp = blockIdx.x, h = blockIdx.y, b = blockIdx.z;
    const float* src = inp==0 ? x : (inp==1 ? xf : xr);
    const int tid = threadIdx.x;
    const float* sp = src + (size_t)b*CHW + (size_t)h*128;
    for (int u = tid; u < 4096; u += 256){
        int c = u >> 5, q = u & 31;
        float4 v = *(const float4*)(sp + (size_t)c*HW + 4*q);
        float* d = tl + c*133 + 4*q;
        d[0]=v.x; d[1]=v.y; d[2]=v.z; d[3]=v.w;
    }
    __syncthreads();
    const size_t obase = ((size_t)inp*1024 + b*128 + h) * 16384;
    const size_t bbase = (((size_t)b*130 + (h+1))*130)*384;
    for (int u = tid; u < 4096; u += 256){
        int cg = u & 31, w = u >> 5;
        float v0 = tl[(4*cg+0)*133 + w], v1 = tl[(4*cg+1)*133 + w];
        float v2 = tl[(4*cg+2)*133 + w], v3 = tl[(4*cg+3)*133 + w];
        uint2 pv = make_uint2(pack_f16(v0, v1), pack_f16(v2, v3));
        *(uint2*)&g_tih[obase + (size_t)w*128 + 4*cg] = pv;
        if (inp == 0)
            *(uint2*)&g_bhi[bbase + (size_t)(w+1)*384 + 256 + 4*cg] = pv;
    }
}

// ============ compose 1x1 weights: which 0:Wx 1:W1@Wx 2:W2@Wx 3:Wf 4:Wr =====
__global__ __launch_bounds__(256) void wcompose_kernel(
    const float* __restrict__ Wx, const float* __restrict__ bx,
    const float* __restrict__ W1, const float* __restrict__ b1,
    const float* __restrict__ W2, const float* __restrict__ b2,
    const float* __restrict__ Wf, const float* __restrict__ bf,
    const float* __restrict__ Wr, const float* __restrict__ br_)
{
    extern __shared__ float S[];
    const int which = blockIdx.x, tid = threadIdx.x;
    if (which == 0 || which >= 3){
        const float* Ws = which==0 ? Wx : (which==3 ? Wf : Wr);
        const float* bs = which==0 ? bx : (which==3 ? bf : br_);
        for (int i = tid; i < 16384; i += 256) g_wcf[which*16384 + i] = Ws[i];
        if (tid < 128) g_bcf[which*128 + tid] = bs[tid];
        return;
    }
    const float* Wo = (which==1) ? W1 : W2;
    const float* bo = (which==1) ? b1 : b2;
    for (int i = tid; i < 16384; i += 256) S[i] = Wx[i];
    __syncthreads();
    int r = tid >> 1, c0 = (tid & 1) * 64;
    float acc[64];
#pragma unroll
    for (int j = 0; j < 64; j++) acc[j] = 0.f;
    for (int k = 0; k < 128; k++){
        float a = Wo[r*128 + k];
#pragma unroll
        for (int j = 0; j < 64; j++) acc[j] = fmaf(a, S[k*128 + c0 + j], acc[j]);
    }
    for (int j = 0; j < 64; j++) g_wcf[which*16384 + r*128 + c0 + j] = acc[j];
    if (tid < 128){
        float s = bo[tid];
        for (int k = 0; k < 128; k++) s = fmaf(Wo[tid*128 + k], bx[k], s);
        g_bcf[which*128 + tid] = s;
    }
}

// split composed weights to fp16 panels [which][pn][o][ci64]
__global__ void wsplit_kernel()
{
    int idx = blockIdx.x*256 + threadIdx.x;
    if (idx >= 81920) return;
    int ci = idx & 63, o = (idx >> 6) & 127, pn = (idx >> 13) & 1, which = idx >> 14;
    g_wsh[idx] = __half_as_ushort(__float2half(g_wcf[which*16384 + o*128 + pn*64 + ci]));
}

// ============ conv1x1: single-pass fp16, 64KB smem, double-buffered =========
__global__ __launch_bounds__(256, 2) void conv1x1_mma(void)
{
    extern __shared__ char dsm[];
    const int tid = threadIdx.x, l = tid & 31, wid = tid >> 5;
    const int mw = wid & 1, nw = wid >> 1;
    const int which = blockIdx.x, h = blockIdx.y, b = blockIdx.z;
    const uint32_t sb = smem_u32(dsm);
    const int inp = (which < 3) ? 0 : which - 2;

    const char* wH = (const char*)g_wsh + which*32768;
    const size_t slab = ((size_t)inp*1024 + b*128 + h)*32768;
    const char* tH = (const char*)g_tih + slab;

    auto stage = [&](int pn){
        uint32_t base = pn*32768;
        for (int u = tid; u < 1024; u += 256){
            CP16(sb + base + SWZ((uint32_t)(u*16)), wH + pn*16384 + u*16);
            int w = u >> 3, j = u & 7;
            CP16(sb + base + 16384 + SWZ((uint32_t)(w*128 + j*16)), tH + w*256 + pn*128 + j*16);
        }
    };

    float acc[4][4][4];
#pragma unroll
    for (int f=0;f<4;f++)
#pragma unroll
        for (int g=0;g<4;g++)
#pragma unroll
            for (int e=0;e<4;e++) acc[f][g][e] = 0.f;

    stage(0); CP_COMMIT();
    stage(1); CP_COMMIT();
    CP_WAIT1(); __syncthreads();
    gemm64f(sb, 0, 16384, l, mw, nw, acc);
    CP_WAIT0(); __syncthreads();
    gemm64f(sb, 32768, 49152, l, mw, nw, acc);

    const size_t base = (size_t)(b*128 + h)*16384;
    if (which == 0){
        __syncthreads();
        unsigned short* tile = (unsigned short*)dsm;
#pragma unroll
        for (int f = 0; f < 4; f++){
            int r1 = mw*64 + f*16 + (l>>2), r2 = r1 + 8;
            float b1v = g_bcf[r1], b2v = g_bcf[r2];
#pragma unroll
            for (int g = 0; g < 4; g++){
                int w = nw*32 + g*8 + 2*(l & 3);
                tile[(size_t)w*128 + r1]     = __half_as_ushort(__float2half(acc[f][g][0] + b1v));
                tile[(size_t)(w+1)*128 + r1] = __half_as_ushort(__float2half(acc[f][g][1] + b1v));
                tile[(size_t)w*128 + r2]     = __half_as_ushort(__float2half(acc[f][g][2] + b2v));
                tile[(size_t)(w+1)*128 + r2] = __half_as_ushort(__float2half(acc[f][g][3] + b2v));
            }
        }
        __syncthreads();
        for (int u = tid; u < 2048; u += 256){
            *(uint4*)((char*)(g_xph + base) + u*16) = *(uint4*)(dsm + u*16);
        }
    } else {
        unsigned short* oh;
        if (which == 1) oh = g_x1h;
        else if (which == 2) oh = g_x2h;
        else if (which == 3) oh = g_xfh;
        else oh = g_xrh;
#pragma unroll
        for (int f = 0; f < 4; f++){
            int r1 = mw*64 + f*16 + (l>>2), r2 = r1 + 8;
            float b1v = g_bcf[which*128 + r1], b2v = g_bcf[which*128 + r2];
#pragma unroll
            for (int g = 0; g < 4; g++){
                int w = nw*32 + g*8 + 2*(l & 3);
                *(unsigned*)&oh[base + (size_t)r1*128 + w] = pack_f16(acc[f][g][0] + b1v, acc[f][g][1] + b1v);
                *(unsigned*)&oh[base + (size_t)r2*128 + w] = pack_f16(acc[f][g][2] + b2v, acc[f][g][3] + b2v);
            }
        }
    }
}

// ============ attention: single-pass fp16, 64KB smem ========================
__global__ __launch_bounds__(256, 2) void attn_mma(void)
{
    extern __shared__ char dsm[];
    __shared__ float red[16];
    const int tid = threadIdx.x, l = tid & 31, wid = tid >> 5;
    const int mw = wid & 1, nw = wid >> 1;
    const int br = blockIdx.x, h = blockIdx.y, b = blockIdx.z;
    const uint32_t sb = smem_u32(dsm);
    const size_t slab = (size_t)(b*128 + h) * 32768;
    const char* aH = (const char*)(br ? g_x2h : g_x1h) + slab;
    const char* bH = (const char*)(br ? g_xrh : g_xfh) + slab;
    const char* pH = (const char*)g_xph + slab;

    for (int u = tid; u < 2048; u += 256){
        int c = u >> 4, j = u & 15;
        int pn = j >> 3, jj = j & 7;
        uint32_t d = pn*16384 + SWZ((uint32_t)(c*128 + jj*16));
        CP16(sb + d,         aH + c*256 + pn*128 + jj*16);
        CP16(sb + 32768 + d, bH + c*256 + pn*128 + jj*16);
    }
    CP_COMMIT(); CP_WAIT0(); __syncthreads();

    float acc[4][4][4];
#pragma unroll
    for (int f=0;f<4;f++)
#pragma unroll
        for (int g=0;g<4;g++)
#pragma unroll
            for (int e=0;e<4;e++) acc[f][g][e] = 0.f;
    gemm64f(sb, 0,     32768, l, mw, nw, acc);
    gemm64f(sb, 16384, 49152, l, mw, nw, acc);

    float ls = 0.f, lq = 0.f;
#pragma unroll
    for (int f=0;f<4;f++)
#pragma unroll
        for (int g=0;g<4;g++)
#pragma unroll
            for (int e=0;e<4;e++){ ls += acc[f][g][e]; lq += acc[f][g][e]*acc[f][g][e]; }
    block_reduce_2(ls, lq, red);
    float mean = ls * (1.f/16384.f);
    float inv  = rsqrtf(lq * (1.f/16384.f) - mean*mean + EPSF);

    for (int u = tid; u < 2048; u += 256){
        int w = u >> 4, j = u & 15;
        int pn = j >> 3, jj = j & 7;
        CP16(sb + 32768 + pn*16384 + SWZ((uint32_t)(w*128 + jj*16)),
             pH + w*256 + pn*128 + jj*16);
    }
    CP_COMMIT();

#pragma unroll
    for (int f = 0; f < 4; f++){
        int c1 = mw*64 + f*16 + (l>>2), c2 = c1 + 8;
#pragma unroll
        for (int g = 0; g < 4; g++){
            int dd = nw*32 + g*8 + 2*(l & 3);
            uint32_t pn = (uint32_t)(dd >> 6)*16384;
            uint32_t byt = (uint32_t)((dd & 63)*2);
            *(unsigned*)(dsm + pn + SWZ((uint32_t)(c1*128) + byt)) =
                pack_f16((acc[f][g][0]-mean)*inv, (acc[f][g][1]-mean)*inv);
            *(unsigned*)(dsm + pn + SWZ((uint32_t)(c2*128) + byt)) =
                pack_f16((acc[f][g][2]-mean)*inv, (acc[f][g][3]-mean)*inv);
        }
    }
    CP_WAIT0(); __syncthreads();

#pragma unroll
    for (int f=0;f<4;f++)
#pragma unroll
        for (int g=0;g<4;g++)
#pragma unroll
            for (int e=0;e<4;e++) acc[f][g][e] = 0.f;
    gemm64f(sb, 0,     32768, l, mw, nw, acc);
    gemm64f(sb, 16384, 49152, l, mw, nw, acc);

    ls = 0.f; lq = 0.f;
#pragma unroll
    for (int f=0;f<4;f++)
#pragma unroll
        for (int g=0;g<4;g++)
#pragma unroll
            for (int e=0;e<4;e++){ ls += acc[f][g][e]; lq += acc[f][g][e]*acc[f][g][e]; }
    block_reduce_2(ls, lq, red);
    mean = ls * (1.f/16384.f);
    inv  = rsqrtf(lq * (1.f/16384.f) - mean*mean + EPSF);

    unsigned short* tile = (unsigned short*)dsm;
#pragma unroll
    for (int f = 0; f < 4; f++){
        int c1 = mw*64 + f*16 + (l>>2), c2 = c1 + 8;
#pragma unroll
        for (int g = 0; g < 4; g++){
            int w = nw*32 + g*8 + 2*(l & 3);
            tile[(size_t)w*128 + c1]     = __half_as_ushort(__float2half((acc[f][g][0]-mean)*inv));
            tile[(size_t)(w+1)*128 + c1] = __half_as_ushort(__float2half((acc[f][g][1]-mean)*inv));
            tile[(size_t)w*128 + c2]     = __half_as_ushort(__float2half((acc[f][g][2]-mean)*inv));
            tile[(size_t)(w+1)*128 + c2] = __half_as_ushort(__float2half((acc[f][g][3]-mean)*inv));
        }
    }
    __syncthreads();
    const size_t rowb = (((size_t)b*130 + (h+1))*130 + 1)*384 + br*128;
    for (int u = tid; u < 2048; u += 256){
        int w = u >> 4, j = u & 15;
        uint4 v = *(uint4*)(dsm + w*256 + j*16);
        *(uint4*)((char*)g_bhi + (rowb + (size_t)w*384)*2 + j*16) = v;
    }
}

// ============ conv3x3 weight prep: fp16 [tap][chunk][o][ci] =================
__global__ void presplit_kernel(const float* __restrict__ Wm)
{
    int idx = blockIdx.x*256 + threadIdx.x;
    if (idx >= 9*6*384*64) return;
    int ci = idx & 63;
    int o  = (idx >> 6) % 384;
    int r  = idx >> 6; r /= 384;
    int chunk = r % 6, tap = r / 6;
    float v = Wm[(size_t)o*3456 + (chunk*64 + ci)*9 + tap];
    g_wh[idx] = __half_as_ushort(__float2half(v));
}

// ====== conv3x3 fp16 single-pass, M=128/N=128, 3-stage ring, 2 CTAs/SM ======
#define OFF_AH 0
#define OFF_BH 16384
#define STAGE  33792

__global__ __launch_bounds__(256, 2) void conv3x3_tc(
    const float* __restrict__ bm, const float* __restrict__ gamma,
    const float* __restrict__ beta, const float* __restrict__ rmean,
    const float* __restrict__ rvar, float* __restrict__ out)
{
    extern __shared__ char dsm[];
    const int tid = threadIdx.x, l = tid & 31, wid = tid >> 5;
    const int mw = wid & 1, nw = wid >> 1;
    const int h = blockIdx.y, o0 = blockIdx.x << 7, b = blockIdx.z;
    const uint32_t sb = smem_u32(dsm);

    float acc[4][4][4];
#pragma unroll
    for (int f=0;f<4;f++)
#pragma unroll
        for (int g=0;g<4;g++)
#pragma unroll
            for (int e=0;e<4;e++) acc[f][g][e] = 0.f;

    auto stage = [&](int it, int st){
        int tap = it/6, chunk = it - tap*6;
        int kh = tap/3;
        uint32_t s0 = sb + st*STAGE;
        const char* srcAh = (const char*)g_wh + (((size_t)tap*6 + chunk)*384 + o0)*128;
        for (int u = tid; u < 1024; u += 256){
            CP16(s0 + OFF_AH + SWZ(u*16), srcAh + u*16);
        }
        size_t rowbase = ((size_t)b*130 + (h+kh))*130*768 + (size_t)chunk*128;
        const char* BH = (const char*)g_bhi;
        for (int u = tid; u < 1040; u += 256){
            int wp = u >> 3, j = u & 7;
            CP16(s0 + OFF_BH + SWZ(wp*128 + j*16), BH + rowbase + (size_t)wp*768 + j*16);
        }
    };

    stage(0, 0); CP_COMMIT();
    stage(1, 1); CP_COMMIT();

    for (int it = 0; it < 54; it++){
        if (it + 1 < 54) CP_WAIT1(); else CP_WAIT0();
        __syncthreads();

        const int kw = (it/6) % 3;
        const uint32_t s0 = sb + (it % 3)*STAGE;
#pragma unroll
        for (int ks = 0; ks < 4; ks++){
            uint32_t ah[4][4], bh[4][2];
            const uint32_t abyte = ks*32 + ((l>>4)<<4);
#pragma unroll
            for (int f = 0; f < 4; f++){
                int row = mw*64 + f*16 + (l & 15);
                uint32_t off = SWZ((uint32_t)(row*128) + abyte);
                LDSM4(ah[f][0],ah[f][1],ah[f][2],ah[f][3], s0 + OFF_AH + off);
            }
            const uint32_t bbyte = ks*32 + (((l>>3)&1)<<4);
#pragma unroll
            for (int g2 = 0; g2 < 2; g2++){
                int rowb = nw*32 + g2*16 + kw + (l & 7) + ((l>>4)<<3);
                uint32_t off = SWZ((uint32_t)(rowb*128) + bbyte);
                uint32_t t0,t1,t2,t3;
                LDSM4(t0,t1,t2,t3, s0 + OFF_BH + off);
                bh[g2*2][0]=t0; bh[g2*2][1]=t1; bh[g2*2+1][0]=t2; bh[g2*2+1][1]=t3;
            }
#pragma unroll
            for (int f = 0; f < 4; f++)
#pragma unroll
                for (int g = 0; g < 4; g++)
                    MMAF16(acc[f][g], ah[f], bh[g]);
        }

        if (it + 2 < 54){ stage(it+2, (it+2) % 3); CP_COMMIT(); }
    }

#pragma unroll
    for (int f = 0; f < 4; f++){
        int o1 = o0 + mw*64 + f*16 + (l >> 2);
        int o2 = o1 + 8;
        float sc1 = gamma[o1] * rsqrtf(rvar[o1] + EPSF);
        float sh1 = beta[o1] + (bm[o1] - rmean[o1]) * sc1;
        float sc2 = gamma[o2] * rsqrtf(rvar[o2] + EPSF);
        float sh2 = beta[o2] + (bm[o2] - rmean[o2]) * sc2;
        float* r1 = out + ((size_t)(b*384 + o1))*HW + (size_t)h*128;
        float* r2 = out + ((size_t)(b*384 + o2))*HW + (size_t)h*128;
#pragma unroll
        for (int g = 0; g < 4; g++){
            int w = nw*32 + g*8 + 2*(l & 3);
            float2 v1, v2;
            v1.x = fmaxf(fmaf(acc[f][g][0], sc1, sh1), 0.f);
            v1.y = fmaxf(fmaf(acc[f][g][1], sc1, sh1), 0.f);
            v2.x = fmaxf(fmaf(acc[f][g][2], sc2, sh2), 0.f);
            v2.y = fmaxf(fmaf(acc[f][g][3], sc2, sh2), 0.f);
            *(float2*)(r1 + w) = v1;
            *(float2*)(r2 + w) = v2;
        }
    }
}

// =============================================================================
extern "C" void kernel_launch(void* const* d_in, const int* in_sizes, int n_in,
                              void* d_out, int out_size)
{
    const float* x  = (const float*)d_in[0];
    const float* xf = (const float*)d_in[1];
    const float* xr = (const float*)d_in[2];
    const float* Wx = (const float*)d_in[3];
    const float* bx = (const float*)d_in[4];
    const float* W1 = (const float*)d_in[5];
    const float* b1 = (const float*)d_in[6];
    const float* W2 = (const float*)d_in[7];
    const float* b2 = (const float*)d_in[8];
    const float* Wf = (const float*)d_in[9];
    const float* bf = (const float*)d_in[10];
    const float* Wr = (const float*)d_in[11];
    const float* br_ = (const float*)d_in[12];
    const float* Wm = (const float*)d_in[13];
    const float* bm = (const float*)d_in[14];
    const float* gamma = (const float*)d_in[15];
    const float* beta  = (const float*)d_in[16];
    const float* rmean = (const float*)d_in[17];
    const float* rvar  = (const float*)d_in[18];
    float* out = (float*)d_out;

    cudaFuncSetAttribute(xpose_cvt,   cudaFuncAttributeMaxDynamicSharedMemorySize, 68096);
    cudaFuncSetAttribute(wcompose_kernel, cudaFuncAttributeMaxDynamicSharedMemorySize, 65536);
    cudaFuncSetAttribute(conv1x1_mma, cudaFuncAttributeMaxDynamicSharedMemorySize, 65536);
    cudaFuncSetAttribute(attn_mma,    cudaFuncAttributeMaxDynamicSharedMemorySize, 65536);
    cudaFuncSetAttribute(conv3x3_tc,  cudaFuncAttributeMaxDynamicSharedMemorySize, 3*STAGE);

    xpose_cvt<<<dim3(3, 128, 8), 256, 68096>>>(x, xf, xr);
    wcompose_kernel<<<5, 256, 65536>>>(Wx, bx, W1, b1, W2, b2, Wf, bf, Wr, br_);
    wsplit_kernel<<<320, 256>>>();
    conv1x1_mma<<<dim3(5, 128, 8), 256, 65536>>>();
    attn_mma<<<dim3(2, 128, 8), 256, 65536>>>();
    presplit_kernel<<<5184, 256>>>(Wm);
    conv3x3_tc<<<dim3(3, 128, 8), 256, 3*STAGE>>>(bm, gamma, beta, rmean, rvar, out);
}

// round 12
// speedup vs baseline: 1.0892x; 1.0282x over previous
#include <cuda_runtime.h>
#include <cuda_bf16.h>
#include <cuda_fp16.h>
#include <cstdint>

#define EPSF 1e-5f
#define HW   16384
#define CHW  2097152

// ---------------- scratch (static device memory) ----------------
__device__ float g_wcf[5*16384];                        // composed 1x1 weights fp32
__device__ float g_bcf[5*128];                          // composed biases
__device__ __align__(16) unsigned short g_wsh[5*2*128*64];   // fp16 [which][pn][o][ci64]
__device__ __align__(16) unsigned short g_tih[3ull*8*CHW];   // fp16 inputs T: [inp][b][h][w][c]
__device__ __align__(16) unsigned short g_x1h[8*CHW];        // fp16 [b][h][c][w]
__device__ __align__(16) unsigned short g_x2h[8*CHW];
__device__ __align__(16) unsigned short g_xfh[8*CHW];
__device__ __align__(16) unsigned short g_xrh[8*CHW];
__device__ __align__(16) unsigned short g_xph[8*CHW];        // fp16 [b][h][w][d]
__device__ unsigned short g_wh[9*6*384*64];             // conv3x3 W fp16: [tap][chunk][o][ci]
__device__ unsigned short g_bhi[8ull*130*130*384];      // conv3x3 in fp16: [b][hp][wp][ci]

// ---------------- helpers ----------------
__device__ __forceinline__ uint32_t smem_u32(const void* p){
    uint32_t a; asm("{ .reg .u64 t; cvta.to.shared.u64 t, %1; cvt.u32.u64 %0, t; }"
                    : "=r"(a) : "l"(p)); return a;
}
#define SWZ(x) ((x) ^ (((x)>>3)&0x70))
#define CP16(dst, src) asm volatile("cp.async.cg.shared.global [%0], [%1], 16;" \
    :: "r"((uint32_t)(dst)), "l"((const void*)(src)) : "memory")
#define CP_COMMIT() asm volatile("cp.async.commit_group;" ::: "memory")
#define CP_WAIT0()  asm volatile("cp.async.wait_group 0;" ::: "memory")
#define CP_WAIT1()  asm volatile("cp.async.wait_group 1;" ::: "memory")
#define LDSM4(r0,r1,r2,r3,a) asm volatile( \
    "ldmatrix.sync.aligned.m8n8.x4.shared.b16 {%0,%1,%2,%3}, [%4];" \
    : "=r"(r0),"=r"(r1),"=r"(r2),"=r"(r3) : "r"(a))
#define MMAF16(c,a,b) asm volatile( \
    "mma.sync.aligned.m16n8k16.row.col.f32.f16.f16.f32 " \
    "{%0,%1,%2,%3},{%4,%5,%6,%7},{%8,%9},{%0,%1,%2,%3};" \
    : "+f"((c)[0]),"+f"((c)[1]),"+f"((c)[2]),"+f"((c)[3]) \
    : "r"((a)[0]),"r"((a)[1]),"r"((a)[2]),"r"((a)[3]), "r"((b)[0]),"r"((b)[1]))

__device__ __forceinline__ unsigned pack_f16(float v0, float v1){
    unsigned hp; asm("cvt.rn.f16x2.f32 %0, %1, %2;" : "=r"(hp) : "f"(v1), "f"(v0));
    return hp;
}

// 128x128x64 GEMM chunk, single-pass fp16. a0/b0 = byte offsets of panels in smem.
__device__ __forceinline__ void gemm64f(uint32_t sb, uint32_t a0, uint32_t b0,
                                        int l, int mw, int nw, float acc[4][4][4])
{
#pragma unroll
    for (int ks = 0; ks < 4; ks++){
        uint32_t ah[4][4], bh[4][2];
        const uint32_t abyte = ks*32 + ((l>>4)<<4);
#pragma unroll
        for (int f = 0; f < 4; f++){
            int row = mw*64 + f*16 + (l & 15);
            uint32_t off = SWZ((uint32_t)(row*128) + abyte);
            LDSM4(ah[f][0],ah[f][1],ah[f][2],ah[f][3], sb + a0 + off);
        }
        const uint32_t bbyte = ks*32 + (((l>>3)&1)<<4);
#pragma unroll
        for (int g2 = 0; g2 < 2; g2++){
            int rowb = nw*32 + g2*16 + (l & 7) + ((l>>4)<<3);
            uint32_t off = SWZ((uint32_t)(rowb*128) + bbyte);
            uint32_t t0,t1,t2,t3;
            LDSM4(t0,t1,t2,t3, sb + b0 + off);
            bh[g2*2][0]=t0; bh[g2*2][1]=t1; bh[g2*2+1][0]=t2; bh[g2*2+1][1]=t3;
        }
#pragma unroll
        for (int f = 0; f < 4; f++)
#pragma unroll
            for (int g = 0; g < 4; g++)
                MMAF16(acc[f][g], ah[f], bh[g]);
    }
}

__device__ __forceinline__ void block_reduce_2(float& s, float& q, float* red)
{
#pragma unroll
    for (int off=16; off>0; off>>=1){
        s += __shfl_down_sync(0xffffffffu, s, off);
        q += __shfl_down_sync(0xffffffffu, q, off);
    }
    const int wid = threadIdx.x >> 5;
    if ((threadIdx.x & 31) == 0){ red[wid] = s; red[8+wid] = q; }
    __syncthreads();
    s = 0.f; q = 0.f;
#pragma unroll
    for (int i=0;i<8;i++){ s += red[i]; q += red[8+i]; }
    __syncthreads();
}

// ==== transpose+convert: [b][c][h][w] -> [inp][b][h][w][c] fp16; inp0 also -> g_bhi ====
__global__ __launch_bounds__(256) void xpose_cvt(const float* __restrict__ x,
    const float* __restrict__ xf, const float* __restrict__ xr)
{
    extern __shared__ float tl[];   // [128][133]
    const int inp = blockIdx.x, h = blockIdx.y, b = blockIdx.z;
    const float* src = inp==0 ? x : (inp==1 ? xf : xr);
    const int tid = threadIdx.x;
    const float* sp = src + (size_t)b*CHW + (size_t)h*128;
    for (int u = tid; u < 4096; u += 256){
        int c = u >> 5, q = u & 31;
        float4 v = *(const float4*)(sp + (size_t)c*HW + 4*q);
        float* d = tl + c*133 + 4*q;
        d[0]=v.x; d[1]=v.y; d[2]=v.z; d[3]=v.w;
    }
    __syncthreads();
    const size_t obase = ((size_t)inp*1024 + b*128 + h) * 16384;
    const size_t bbase = (((size_t)b*130 + (h+1))*130)*384;
    for (int u = tid; u < 4096; u += 256){
        int cg = u & 31, w = u >> 5;
        float v0 = tl[(4*cg+0)*133 + w], v1 = tl[(4*cg+1)*133 + w];
        float v2 = tl[(4*cg+2)*133 + w], v3 = tl[(4*cg+3)*133 + w];
        uint2 pv = make_uint2(pack_f16(v0, v1), pack_f16(v2, v3));
        *(uint2*)&g_tih[obase + (size_t)w*128 + 4*cg] = pv;
        if (inp == 0)
            *(uint2*)&g_bhi[bbase + (size_t)(w+1)*384 + 256 + 4*cg] = pv;
    }
}

// ============ compose 1x1 weights: which 0:Wx 1:W1@Wx 2:W2@Wx 3:Wf 4:Wr =====
__global__ __launch_bounds__(256) void wcompose_kernel(
    const float* __restrict__ Wx, const float* __restrict__ bx,
    const float* __restrict__ W1, const float* __restrict__ b1,
    const float* __restrict__ W2, const float* __restrict__ b2,
    const float* __restrict__ Wf, const float* __restrict__ bf,
    const float* __restrict__ Wr, const float* __restrict__ br_)
{
    extern __shared__ float S[];
    const int which = blockIdx.x, tid = threadIdx.x;
    if (which == 0 || which >= 3){
        const float* Ws = which==0 ? Wx : (which==3 ? Wf : Wr);
        const float* bs = which==0 ? bx : (which==3 ? bf : br_);
        for (int i = tid; i < 16384; i += 256) g_wcf[which*16384 + i] = Ws[i];
        if (tid < 128) g_bcf[which*128 + tid] = bs[tid];
        return;
    }
    const float* Wo = (which==1) ? W1 : W2;
    const float* bo = (which==1) ? b1 : b2;
    for (int i = tid; i < 16384; i += 256) S[i] = Wx[i];
    __syncthreads();
    int r = tid >> 1, c0 = (tid & 1) * 64;
    float acc[64];
#pragma unroll
    for (int j = 0; j < 64; j++) acc[j] = 0.f;
    for (int k = 0; k < 128; k++){
        float a = Wo[r*128 + k];
#pragma unroll
        for (int j = 0; j < 64; j++) acc[j] = fmaf(a, S[k*128 + c0 + j], acc[j]);
    }
    for (int j = 0; j < 64; j++) g_wcf[which*16384 + r*128 + c0 + j] = acc[j];
    if (tid < 128){
        float s = bo[tid];
        for (int k = 0; k < 128; k++) s = fmaf(Wo[tid*128 + k], bx[k], s);
        g_bcf[which*128 + tid] = s;
    }
}

// split composed weights to fp16 panels [which][pn][o][ci64]
__global__ void wsplit_kernel()
{
    int idx = blockIdx.x*256 + threadIdx.x;
    if (idx >= 81920) return;
    int ci = idx & 63, o = (idx >> 6) & 127, pn = (idx >> 13) & 1, which = idx >> 14;
    g_wsh[idx] = __half_as_ushort(__float2half(g_wcf[which*16384 + o*128 + pn*64 + ci]));
}

// ==== conv1x1 FUSED: one CTA per (h,b) does all 5 GEMMs; X staged per-input ====
// smem: Wbuf0 @0 (32KB), Wbuf1 @32768 (32KB), X @65536 (32KB)
__global__ __launch_bounds__(256, 2) void conv1x1_mma(void)
{
    extern __shared__ char dsm[];
    const int tid = threadIdx.x, l = tid & 31, wid = tid >> 5;
    const int mw = wid & 1, nw = wid >> 1;
    const int h = blockIdx.x, b = blockIdx.y;
    const uint32_t sb = smem_u32(dsm);
    const size_t base = (size_t)(b*128 + h)*16384;

    auto stage_w = [&](int which, int buf){
        const char* wH = (const char*)g_wsh + which*32768;
        for (int u = tid; u < 2048; u += 256){
            uint32_t d = (uint32_t)buf*32768 + (u >> 10)*16384 + SWZ((uint32_t)((u & 1023)*16));
            CP16(sb + d, wH + u*16);
        }
    };
    auto stage_x = [&](int inp){
        const char* tH = (const char*)g_tih + ((size_t)inp*1024 + b*128 + h)*32768;
        for (int u = tid; u < 2048; u += 256){
            int w = u >> 4, j = u & 15;
            int pn = j >> 3, jj = j & 7;
            CP16(sb + 65536 + pn*16384 + SWZ((uint32_t)(w*128 + jj*16)),
                 tH + w*256 + pn*128 + jj*16);
        }
    };

    float acc[4][4][4];
    auto zacc = [&](){
#pragma unroll
        for (int f=0;f<4;f++)
#pragma unroll
            for (int g=0;g<4;g++)
#pragma unroll
                for (int e=0;e<4;e++) acc[f][g][e] = 0.f;
    };
    auto do_gemm = [&](int buf){
        zacc();
        gemm64f(sb, (uint32_t)buf*32768,         65536, l, mw, nw, acc);
        gemm64f(sb, (uint32_t)buf*32768 + 16384, 81920, l, mw, nw, acc);
    };
    auto epi = [&](unsigned short* oh, int which){
#pragma unroll
        for (int f = 0; f < 4; f++){
            int r1 = mw*64 + f*16 + (l>>2), r2 = r1 + 8;
            float b1v = g_bcf[which*128 + r1], b2v = g_bcf[which*128 + r2];
#pragma unroll
            for (int g = 0; g < 4; g++){
                int w = nw*32 + g*8 + 2*(l & 3);
                *(unsigned*)&oh[base + (size_t)r1*128 + w] = pack_f16(acc[f][g][0] + b1v, acc[f][g][1] + b1v);
                *(unsigned*)&oh[base + (size_t)r2*128 + w] = pack_f16(acc[f][g][2] + b2v, acc[f][g][3] + b2v);
            }
        }
    };

    stage_x(0); stage_w(0, 0); CP_COMMIT();
    stage_w(1, 1); CP_COMMIT();

    // ---- which 0 : Wx -> xp ([w][d] layout via smem transpose in Wbuf0) ----
    CP_WAIT1(); __syncthreads();
    do_gemm(0);
    __syncthreads();
    {
        unsigned short* tile = (unsigned short*)dsm;
#pragma unroll
        for (int f = 0; f < 4; f++){
            int r1 = mw*64 + f*16 + (l>>2), r2 = r1 + 8;
            float b1v = g_bcf[r1], b2v = g_bcf[r2];
#pragma unroll
            for (int g = 0; g < 4; g++){
                int w = nw*32 + g*8 + 2*(l & 3);
                tile[(size_t)w*128 + r1]     = __half_as_ushort(__float2half(acc[f][g][0] + b1v));
                tile[(size_t)(w+1)*128 + r1] = __half_as_ushort(__float2half(acc[f][g][1] + b1v));
                tile[(size_t)w*128 + r2]     = __half_as_ushort(__float2half(acc[f][g][2] + b2v));
                tile[(size_t)(w+1)*128 + r2] = __half_as_ushort(__float2half(acc[f][g][3] + b2v));
            }
        }
        __syncthreads();
        for (int u = tid; u < 2048; u += 256){
            *(uint4*)((char*)(g_xph + base) + u*16) = *(uint4*)(dsm + u*16);
        }
    }
    __syncthreads();
    stage_w(2, 0); CP_COMMIT();

    // ---- which 1 : buf1 -> x1 ----
    CP_WAIT1(); __syncthreads();
    do_gemm(1);
    epi(g_x1h, 1);
    __syncthreads();
    stage_w(3, 1); CP_COMMIT();

    // ---- which 2 : buf0 -> x2 ----
    CP_WAIT1(); __syncthreads();
    do_gemm(0);
    epi(g_x2h, 2);
    __syncthreads();
    stage_x(1); CP_COMMIT();       // xf
    stage_w(4, 0); CP_COMMIT();

    // ---- which 3 : buf1 -> xf ----
    CP_WAIT1(); __syncthreads();
    do_gemm(1);
    epi(g_xfh, 3);
    __syncthreads();
    stage_x(2); CP_COMMIT();       // xr

    // ---- which 4 : buf0 -> xr ----
    CP_WAIT0(); __syncthreads();
    do_gemm(0);
    epi(g_xrh, 4);
}

// ============ attention: single-pass fp16, 64KB smem ========================
__global__ __launch_bounds__(256, 2) void attn_mma(void)
{
    extern __shared__ char dsm[];
    __shared__ float red[16];
    const int tid = threadIdx.x, l = tid & 31, wid = tid >> 5;
    const int mw = wid & 1, nw = wid >> 1;
    const int br = blockIdx.x, h = blockIdx.y, b = blockIdx.z;
    const uint32_t sb = smem_u32(dsm);
    const size_t slab = (size_t)(b*128 + h) * 32768;
    const char* aH = (const char*)(br ? g_x2h : g_x1h) + slab;
    const char* bH = (const char*)(br ? g_xrh : g_xfh) + slab;
    const char* pH = (const char*)g_xph + slab;

    for (int u = tid; u < 2048; u += 256){
        int c = u >> 4, j = u & 15;
        int pn = j >> 3, jj = j & 7;
        uint32_t d = pn*16384 + SWZ((uint32_t)(c*128 + jj*16));
        CP16(sb + d,         aH + c*256 + pn*128 + jj*16);
        CP16(sb + 32768 + d, bH + c*256 + pn*128 + jj*16);
    }
    CP_COMMIT(); CP_WAIT0(); __syncthreads();

    float acc[4][4][4];
#pragma unroll
    for (int f=0;f<4;f++)
#pragma unroll
        for (int g=0;g<4;g++)
#pragma unroll
            for (int e=0;e<4;e++) acc[f][g][e] = 0.f;
    gemm64f(sb, 0,     32768, l, mw, nw, acc);
    gemm64f(sb, 16384, 49152, l, mw, nw, acc);

    float ls = 0.f, lq = 0.f;
#pragma unroll
    for (int f=0;f<4;f++)
#pragma unroll
        for (int g=0;g<4;g++)
#pragma unroll
            for (int e=0;e<4;e++){ ls += acc[f][g][e]; lq += acc[f][g][e]*acc[f][g][e]; }
    block_reduce_2(ls, lq, red);
    float mean = ls * (1.f/16384.f);
    float inv  = rsqrtf(lq * (1.f/16384.f) - mean*mean + EPSF);

    for (int u = tid; u < 2048; u += 256){
        int w = u >> 4, j = u & 15;
        int pn = j >> 3, jj = j & 7;
        CP16(sb + 32768 + pn*16384 + SWZ((uint32_t)(w*128 + jj*16)),
             pH + w*256 + pn*128 + jj*16);
    }
    CP_COMMIT();

#pragma unroll
    for (int f = 0; f < 4; f++){
        int c1 = mw*64 + f*16 + (l>>2), c2 = c1 + 8;
#pragma unroll
        for (int g = 0; g < 4; g++){
            int dd = nw*32 + g*8 + 2*(l & 3);
            uint32_t pn = (uint32_t)(dd >> 6)*16384;
            uint32_t byt = (uint32_t)((dd & 63)*2);
            *(unsigned*)(dsm + pn + SWZ((uint32_t)(c1*128) + byt)) =
                pack_f16((acc[f][g][0]-mean)*inv, (acc[f][g][1]-mean)*inv);
            *(unsigned*)(dsm + pn + SWZ((uint32_t)(c2*128) + byt)) =
                pack_f16((acc[f][g][2]-mean)*inv, (acc[f][g][3]-mean)*inv);
        }
    }
    CP_WAIT0(); __syncthreads();

#pragma unroll
    for (int f=0;f<4;f++)
#pragma unroll
        for (int g=0;g<4;g++)
#pragma unroll
            for (int e=0;e<4;e++) acc[f][g][e] = 0.f;
    gemm64f(sb, 0,     32768, l, mw, nw, acc);
    gemm64f(sb, 16384, 49152, l, mw, nw, acc);

    ls = 0.f; lq = 0.f;
#pragma unroll
    for (int f=0;f<4;f++)
#pragma unroll
        for (int g=0;g<4;g++)
#pragma unroll
            for (int e=0;e<4;e++){ ls += acc[f][g][e]; lq += acc[f][g][e]*acc[f][g][e]; }
    block_reduce_2(ls, lq, red);
    mean = ls * (1.f/16384.f);
    inv  = rsqrtf(lq * (1.f/16384.f) - mean*mean + EPSF);

    unsigned short* tile = (unsigned short*)dsm;
#pragma unroll
    for (int f = 0; f < 4; f++){
        int c1 = mw*64 + f*16 + (l>>2), c2 = c1 + 8;
#pragma unroll
        for (int g = 0; g < 4; g++){
            int w = nw*32 + g*8 + 2*(l & 3);
            tile[(size_t)w*128 + c1]     = __half_as_ushort(__float2half((acc[f][g][0]-mean)*inv));
            tile[(size_t)(w+1)*128 + c1] = __half_as_ushort(__float2half((acc[f][g][1]-mean)*inv));
            tile[(size_t)w*128 + c2]     = __half_as_ushort(__float2half((acc[f][g][2]-mean)*inv));
            tile[(size_t)(w+1)*128 + c2] = __half_as_ushort(__float2half((acc[f][g][3]-mean)*inv));
        }
    }
    __syncthreads();
    const size_t rowb = (((size_t)b*130 + (h+1))*130 + 1)*384 + br*128;
    for (int u = tid; u < 2048; u += 256){
        int w = u >> 4, j = u & 15;
        uint4 v = *(uint4*)(dsm + w*256 + j*16);
        *(uint4*)((char*)g_bhi + (rowb + (size_t)w*384)*2 + j*16) = v;
    }
}

// ============ conv3x3 weight prep: fp16 [tap][chunk][o][ci] =================
__global__ void presplit_kernel(const float* __restrict__ Wm)
{
    int idx = blockIdx.x*256 + threadIdx.x;
    if (idx >= 9*6*384*64) return;
    int ci = idx & 63;
    int o  = (idx >> 6) % 384;
    int r  = idx >> 6; r /= 384;
    int chunk = r % 6, tap = r / 6;
    float v = Wm[(size_t)o*3456 + (chunk*64 + ci)*9 + tap];
    g_wh[idx] = __half_as_ushort(__float2half(v));
}

// ====== conv3x3 fp16, PERSISTENT: 296 CTAs loop over 3072 tiles, 3-stage ring ======
#define OFF_AH 0
#define OFF_BH 16384
#define STAGE  33792
#define NTILE  3072
#define NCTA   296

__global__ __launch_bounds__(256, 2) void conv3x3_tc(
    const float* __restrict__ bm, const float* __restrict__ gamma,
    const float* __restrict__ beta, const float* __restrict__ rmean,
    const float* __restrict__ rvar, float* __restrict__ out)
{
    extern __shared__ char dsm[];
    const int tid = threadIdx.x, l = tid & 31, wid = tid >> 5;
    const int mw = wid & 1, nw = wid >> 1;
    const int bx = blockIdx.x;
    const uint32_t sb = smem_u32(dsm);

    const int nt = (NTILE - bx + NCTA - 1) / NCTA;
    const int total = nt * 54;

    auto stage = [&](int idx){
        int tile = bx + (idx / 54) * NCTA;
        int it = idx % 54;
        int ob = tile % 3; int r = tile / 3;
        int h = r & 127, b2 = r >> 7;
        int o0 = ob << 7;
        int tap = it/6, chunk = it - tap*6, kh = tap/3;
        uint32_t s0 = sb + (uint32_t)(idx % 3)*STAGE;
        const char* srcA = (const char*)g_wh + (((size_t)tap*6 + chunk)*384 + o0)*128;
        for (int u = tid; u < 1024; u += 256){
            CP16(s0 + OFF_AH + SWZ(u*16), srcA + u*16);
        }
        size_t rowbase = ((size_t)b2*130 + (h+kh))*130*768 + (size_t)chunk*128;
        const char* BH = (const char*)g_bhi;
        for (int u = tid; u < 1040; u += 256){
            int wp = u >> 3, j = u & 7;
            CP16(s0 + OFF_BH + SWZ(wp*128 + j*16), BH + rowbase + (size_t)wp*768 + j*16);
        }
    };

    float acc[4][4][4];

    stage(0); CP_COMMIT();
    int staged = 1;
    if (total > 1){ stage(1); CP_COMMIT(); staged = 2; }

    for (int i = 0; i < total; i++){
        if (staged - i - 1 >= 1) CP_WAIT1(); else CP_WAIT0();
        __syncthreads();

        const int tile = bx + (i / 54) * NCTA;
        const int it = i % 54;
        if (it == 0){
#pragma unroll
            for (int f=0;f<4;f++)
#pragma unroll
                for (int g=0;g<4;g++)
#pragma unroll
                    for (int e=0;e<4;e++) acc[f][g][e] = 0.f;
        }

        const int kw = (it/6) % 3;
        const uint32_t s0 = sb + (uint32_t)(i % 3)*STAGE;
#pragma unroll
        for (int ks = 0; ks < 4; ks++){
            uint32_t ah[4][4], bh[4][2];
            const uint32_t abyte = ks*32 + ((l>>4)<<4);
#pragma unroll
            for (int f = 0; f < 4; f++){
                int row = mw*64 + f*16 + (l & 15);
                uint32_t off = SWZ((uint32_t)(row*128) + abyte);
                LDSM4(ah[f][0],ah[f][1],ah[f][2],ah[f][3], s0 + OFF_AH + off);
            }
            const uint32_t bbyte = ks*32 + (((l>>3)&1)<<4);
#pragma unroll
            for (int g2 = 0; g2 < 2; g2++){
                int rowb = nw*32 + g2*16 + kw + (l & 7) + ((l>>4)<<3);
                uint32_t off = SWZ((uint32_t)(rowb*128) + bbyte);
                uint32_t t0,t1,t2,t3;
                LDSM4(t0,t1,t2,t3, s0 + OFF_BH + off);
                bh[g2*2][0]=t0; bh[g2*2][1]=t1; bh[g2*2+1][0]=t2; bh[g2*2+1][1]=t3;
            }
#pragma unroll
            for (int f = 0; f < 4; f++)
#pragma unroll
                for (int g = 0; g < 4; g++)
                    MMAF16(acc[f][g], ah[f], bh[g]);
        }

        if (staged < total){ stage(staged); CP_COMMIT(); staged++; }

        if (it == 53){
            int ob = tile % 3; int r = tile / 3;
            int h = r & 127, b2 = r >> 7;
            int o0 = ob << 7;
#pragma unroll
            for (int f = 0; f < 4; f++){
                int o1 = o0 + mw*64 + f*16 + (l >> 2);
                int o2 = o1 + 8;
                float sc1 = gamma[o1] * rsqrtf(rvar[o1] + EPSF);
                float sh1 = beta[o1] + (bm[o1] - rmean[o1]) * sc1;
                float sc2 = gamma[o2] * rsqrtf(rvar[o2] + EPSF);
                float sh2 = beta[o2] + (bm[o2] - rmean[o2]) * sc2;
                float* r1 = out + ((size_t)(b2*384 + o1))*HW + (size_t)h*128;
                float* r2 = out + ((size_t)(b2*384 + o2))*HW + (size_t)h*128;
#pragma unroll
                for (int g = 0; g < 4; g++){
                    int w = nw*32 + g*8 + 2*(l & 3);
                    float2 v1, v2;
                    v1.x = fmaxf(fmaf(acc[f][g][0], sc1, sh1), 0.f);
                    v1.y = fmaxf(fmaf(acc[f][g][1], sc1, sh1), 0.f);
                    v2.x = fmaxf(fmaf(acc[f][g][2], sc2, sh2), 0.f);
                    v2.y = fmaxf(fmaf(acc[f][g][3], sc2, sh2), 0.f);
                    *(float2*)(r1 + w) = v1;
                    *(float2*)(r2 + w) = v2;
                }
            }
        }
    }
}

// =============================================================================
extern "C" void kernel_launch(void* const* d_in, const int* in_sizes, int n_in,
                              void* d_out, int out_size)
{
    const float* x  = (const float*)d_in[0];
    const float* xf = (const float*)d_in[1];
    const float* xr = (const float*)d_in[2];
    const float* Wx = (const float*)d_in[3];
    const float* bx = (const float*)d_in[4];
    const float* W1 = (const float*)d_in[5];
    const float* b1 = (const float*)d_in[6];
    const float* W2 = (const float*)d_in[7];
    const float* b2 = (const float*)d_in[8];
    const float* Wf = (const float*)d_in[9];
    const float* bf = (const float*)d_in[10];
    const float* Wr = (const float*)d_in[11];
    const float* br_ = (const float*)d_in[12];
    const float* Wm = (const float*)d_in[13];
    const float* bm = (const float*)d_in[14];
    const float* gamma = (const float*)d_in[15];
    const float* beta  = (const float*)d_in[16];
    const float* rmean = (const float*)d_in[17];
    const float* rvar  = (const float*)d_in[18];
    float* out = (float*)d_out;

    cudaFuncSetAttribute(xpose_cvt,   cudaFuncAttributeMaxDynamicSharedMemorySize, 68096);
    cudaFuncSetAttribute(wcompose_kernel, cudaFuncAttributeMaxDynamicSharedMemorySize, 65536);
    cudaFuncSetAttribute(conv1x1_mma, cudaFuncAttributeMaxDynamicSharedMemorySize, 98304);
    cudaFuncSetAttribute(attn_mma,    cudaFuncAttributeMaxDynamicSharedMemorySize, 65536);
    cudaFuncSetAttribute(conv3x3_tc,  cudaFuncAttributeMaxDynamicSharedMemorySize, 3*STAGE);

    xpose_cvt<<<dim3(3, 128, 8), 256, 68096>>>(x, xf, xr);
    wcompose_kernel<<<5, 256, 65536>>>(Wx, bx, W1, b1, W2, b2, Wf, bf, Wr, br_);
    wsplit_kernel<<<320, 256>>>();
    conv1x1_mma<<<dim3(128, 8), 256, 98304>>>();
    attn_mma<<<dim3(2, 128, 8), 256, 65536>>>();
    presplit_kernel<<<5184, 256>>>(Wm);
    conv3x3_tc<<<NCTA, 256, 3*STAGE>>>(bm, gamma, beta, rmean, rvar, out);
}

// round 13
// speedup vs baseline: 1.1156x; 1.0243x over previous
#include <cuda_runtime.h>
#include <cuda_bf16.h>
#include <cuda_fp16.h>
#include <cstdint>

#define EPSF 1e-5f
#define HW   16384
#define CHW  2097152

// ---------------- scratch (static device memory) ----------------
__device__ float g_wcf[5*16384];                        // composed 1x1 weights fp32
__device__ float g_bcf[5*128];                          // composed biases
__device__ __align__(16) unsigned short g_wsh[5*2*128*64];   // fp16 [which][pn][o][ci64]
__device__ __align__(16) unsigned short g_tih[3ull*8*CHW];   // fp16 inputs T: [inp][b][h][w][c]
__device__ unsigned short g_wh[9*6*384*64];             // conv3x3 W fp16: [tap][chunk][o][ci]
__device__ unsigned short g_bhi[8ull*130*130*384];      // conv3x3 in fp16: [b][hp][wp][ci]

// ---------------- helpers ----------------
__device__ __forceinline__ uint32_t smem_u32(const void* p){
    uint32_t a; asm("{ .reg .u64 t; cvta.to.shared.u64 t, %1; cvt.u32.u64 %0, t; }"
                    : "=r"(a) : "l"(p)); return a;
}
#define SWZ(x) ((x) ^ (((x)>>3)&0x70))
#define CP16(dst, src) asm volatile("cp.async.cg.shared.global [%0], [%1], 16;" \
    :: "r"((uint32_t)(dst)), "l"((const void*)(src)) : "memory")
#define CP_COMMIT() asm volatile("cp.async.commit_group;" ::: "memory")
#define CP_WAIT0()  asm volatile("cp.async.wait_group 0;" ::: "memory")
#define CP_WAIT1()  asm volatile("cp.async.wait_group 1;" ::: "memory")
#define LDSM4(r0,r1,r2,r3,a) asm volatile( \
    "ldmatrix.sync.aligned.m8n8.x4.shared.b16 {%0,%1,%2,%3}, [%4];" \
    : "=r"(r0),"=r"(r1),"=r"(r2),"=r"(r3) : "r"(a))
#define MMAF16(c,a,b) asm volatile( \
    "mma.sync.aligned.m16n8k16.row.col.f32.f16.f16.f32 " \
    "{%0,%1,%2,%3},{%4,%5,%6,%7},{%8,%9},{%0,%1,%2,%3};" \
    : "+f"((c)[0]),"+f"((c)[1]),"+f"((c)[2]),"+f"((c)[3]) \
    : "r"((a)[0]),"r"((a)[1]),"r"((a)[2]),"r"((a)[3]), "r"((b)[0]),"r"((b)[1]))

__device__ __forceinline__ unsigned pack_f16(float v0, float v1){
    unsigned hp; asm("cvt.rn.f16x2.f32 %0, %1, %2;" : "=r"(hp) : "f"(v1), "f"(v0));
    return hp;
}

// 128x128x64 GEMM chunk, single-pass fp16. a0/b0 = byte offsets of panels in smem.
__device__ __forceinline__ void gemm64f(uint32_t sb, uint32_t a0, uint32_t b0,
                                        int l, int mw, int nw, float acc[4][4][4])
{
#pragma unroll
    for (int ks = 0; ks < 4; ks++){
        uint32_t ah[4][4], bh[4][2];
        const uint32_t abyte = ks*32 + ((l>>4)<<4);
#pragma unroll
        for (int f = 0; f < 4; f++){
            int row = mw*64 + f*16 + (l & 15);
            uint32_t off = SWZ((uint32_t)(row*128) + abyte);
            LDSM4(ah[f][0],ah[f][1],ah[f][2],ah[f][3], sb + a0 + off);
        }
        const uint32_t bbyte = ks*32 + (((l>>3)&1)<<4);
#pragma unroll
        for (int g2 = 0; g2 < 2; g2++){
            int rowb = nw*32 + g2*16 + (l & 7) + ((l>>4)<<3);
            uint32_t off = SWZ((uint32_t)(rowb*128) + bbyte);
            uint32_t t0,t1,t2,t3;
            LDSM4(t0,t1,t2,t3, sb + b0 + off);
            bh[g2*2][0]=t0; bh[g2*2][1]=t1; bh[g2*2+1][0]=t2; bh[g2*2+1][1]=t3;
        }
#pragma unroll
        for (int f = 0; f < 4; f++)
#pragma unroll
            for (int g = 0; g < 4; g++)
                MMAF16(acc[f][g], ah[f], bh[g]);
    }
}

__device__ __forceinline__ void block_reduce_2(float& s, float& q, float* red)
{
#pragma unroll
    for (int off=16; off>0; off>>=1){
        s += __shfl_down_sync(0xffffffffu, s, off);
        q += __shfl_down_sync(0xffffffffu, q, off);
    }
    const int wid = threadIdx.x >> 5;
    if ((threadIdx.x & 31) == 0){ red[wid] = s; red[8+wid] = q; }
    __syncthreads();
    s = 0.f; q = 0.f;
#pragma unroll
    for (int i=0;i<8;i++){ s += red[i]; q += red[8+i]; }
    __syncthreads();
}

// ==== transpose+convert: [b][c][h][w] -> [inp][b][h][w][c] fp16; inp0 also -> g_bhi ====
__global__ __launch_bounds__(256) void xpose_cvt(const float* __restrict__ x,
    const float* __restrict__ xf, const float* __restrict__ xr)
{
    extern __shared__ float tl[];   // [128][133]
    const int inp = blockIdx.x, h = blockIdx.y, b = blockIdx.z;
    const float* src = inp==0 ? x : (inp==1 ? xf : xr);
    const int tid = threadIdx.x;
    const float* sp = src + (size_t)b*CHW + (size_t)h*128;
    for (int u = tid; u < 4096; u += 256){
        int c = u >> 5, q = u & 31;
        float4 v = *(const float4*)(sp + (size_t)c*HW + 4*q);
        float* d = tl + c*133 + 4*q;
        d[0]=v.x; d[1]=v.y; d[2]=v.z; d[3]=v.w;
    }
    __syncthreads();
    const size_t obase = ((size_t)inp*1024 + b*128 + h) * 16384;
    const size_t bbase = (((size_t)b*130 + (h+1))*130)*384;
    for (int u = tid; u < 4096; u += 256){
        int cg = u & 31, w = u >> 5;
        float v0 = tl[(4*cg+0)*133 + w], v1 = tl[(4*cg+1)*133 + w];
        float v2 = tl[(4*cg+2)*133 + w], v3 = tl[(4*cg+3)*133 + w];
        uint2 pv = make_uint2(pack_f16(v0, v1), pack_f16(v2, v3));
        *(uint2*)&g_tih[obase + (size_t)w*128 + 4*cg] = pv;
        if (inp == 0)
            *(uint2*)&g_bhi[bbase + (size_t)(w+1)*384 + 256 + 4*cg] = pv;
    }
}

// ============ compose 1x1 weights: which 0:Wx 1:W1@Wx 2:W2@Wx 3:Wf 4:Wr =====
__global__ __launch_bounds__(256) void wcompose_kernel(
    const float* __restrict__ Wx, const float* __restrict__ bx,
    const float* __restrict__ W1, const float* __restrict__ b1,
    const float* __restrict__ W2, const float* __restrict__ b2,
    const float* __restrict__ Wf, const float* __restrict__ bf,
    const float* __restrict__ Wr, const float* __restrict__ br_)
{
    extern __shared__ float S[];
    const int which = blockIdx.x, tid = threadIdx.x;
    if (which == 0 || which >= 3){
        const float* Ws = which==0 ? Wx : (which==3 ? Wf : Wr);
        const float* bs = which==0 ? bx : (which==3 ? bf : br_);
        for (int i = tid; i < 16384; i += 256) g_wcf[which*16384 + i] = Ws[i];
        if (tid < 128) g_bcf[which*128 + tid] = bs[tid];
        return;
    }
    const float* Wo = (which==1) ? W1 : W2;
    const float* bo = (which==1) ? b1 : b2;
    for (int i = tid; i < 16384; i += 256) S[i] = Wx[i];
    __syncthreads();
    int r = tid >> 1, c0 = (tid & 1) * 64;
    float acc[64];
#pragma unroll
    for (int j = 0; j < 64; j++) acc[j] = 0.f;
    for (int k = 0; k < 128; k++){
        float a = Wo[r*128 + k];
#pragma unroll
        for (int j = 0; j < 64; j++) acc[j] = fmaf(a, S[k*128 + c0 + j], acc[j]);
    }
    for (int j = 0; j < 64; j++) g_wcf[which*16384 + r*128 + c0 + j] = acc[j];
    if (tid < 128){
        float s = bo[tid];
        for (int k = 0; k < 128; k++) s = fmaf(Wo[tid*128 + k], bx[k], s);
        g_bcf[which*128 + tid] = s;
    }
}

// split composed weights to fp16 panels [which][pn][o][ci64]
__global__ void wsplit_kernel()
{
    int idx = blockIdx.x*256 + threadIdx.x;
    if (idx >= 81920) return;
    int ci = idx & 63, o = (idx >> 6) & 127, pn = (idx >> 13) & 1, which = idx >> 14;
    g_wsh[idx] = __half_as_ushort(__float2half(g_wcf[which*16384 + o*128 + pn*64 + ci]));
}

// ==== FUSED front end: one CTA per (b,h) does 5 conv GEMMs + both attn branches ====
// smem: XB 0 | W0 32K | W1 64K | XP 96K | X1 128K | X2 160K | XF 192K  (= 224KB)
#define FXB  0u
#define FW0  32768u
#define FW1  65536u
#define FXP  98304u
#define FX1  131072u
#define FX2  163840u
#define FXF  196608u
#define FSMEM 229376

__global__ __launch_bounds__(256) void front_mma(void)
{
    extern __shared__ char dsm[];
    __shared__ float red[16];
    const int tid = threadIdx.x, l = tid & 31, wid = tid >> 5;
    const int mw = wid & 1, nw = wid >> 1;
    const int h = blockIdx.x, b = blockIdx.y;
    const uint32_t sb = smem_u32(dsm);

    auto stage_w = [&](int which, uint32_t off){
        const char* wH = (const char*)g_wsh + which*32768;
        for (int u = tid; u < 2048; u += 256){
            uint32_t d = off + (uint32_t)(u >> 10)*16384 + SWZ((uint32_t)((u & 1023)*16));
            CP16(sb + d, wH + u*16);
        }
    };
    auto stage_x = [&](int inp){
        const char* tH = (const char*)g_tih + ((size_t)inp*1024 + b*128 + h)*32768;
        for (int u = tid; u < 2048; u += 256){
            int w = u >> 4, j = u & 15;
            int pn = j >> 3, jj = j & 7;
            CP16(sb + FXB + pn*16384 + SWZ((uint32_t)(w*128 + jj*16)),
                 tH + w*256 + pn*128 + jj*16);
        }
    };

    float acc[4][4][4];
    auto zacc = [&](){
#pragma unroll
        for (int f=0;f<4;f++)
#pragma unroll
            for (int g=0;g<4;g++)
#pragma unroll
                for (int e=0;e<4;e++) acc[f][g][e] = 0.f;
    };
    auto conv_gemm = [&](uint32_t woff){
        zacc();
        gemm64f(sb, woff,         FXB,         l, mw, nw, acc);
        gemm64f(sb, woff + 16384, FXB + 16384, l, mw, nw, acc);
    };
    // acc (+bias) -> A-panel layout [row=o][k=w] at doff (fp16)
    auto write_Apanels = [&](uint32_t doff, int which){
#pragma unroll
        for (int f = 0; f < 4; f++){
            int c1 = mw*64 + f*16 + (l>>2), c2 = c1 + 8;
            float b1v = g_bcf[which*128 + c1], b2v = g_bcf[which*128 + c2];
#pragma unroll
            for (int g = 0; g < 4; g++){
                int w = nw*32 + g*8 + 2*(l & 3);
                uint32_t pn = (uint32_t)(w >> 6)*16384;
                uint32_t byt = (uint32_t)((w & 63)*2);
                *(unsigned*)(dsm + doff + pn + SWZ((uint32_t)(c1*128) + byt)) =
                    pack_f16(acc[f][g][0] + b1v, acc[f][g][1] + b1v);
                *(unsigned*)(dsm + doff + pn + SWZ((uint32_t)(c2*128) + byt)) =
                    pack_f16(acc[f][g][2] + b2v, acc[f][g][3] + b2v);
            }
        }
    };
    // xp: acc rows are d; store transposed as B panels [row=w][k=d] at FXP (2B stores)
    auto write_xp = [&](){
#pragma unroll
        for (int f = 0; f < 4; f++){
            int d1 = mw*64 + f*16 + (l>>2), d2 = d1 + 8;
            float b1v = g_bcf[d1], b2v = g_bcf[d2];
            uint32_t p1 = (uint32_t)(d1 >> 6)*16384, y1 = (uint32_t)((d1 & 63)*2);
            uint32_t p2 = (uint32_t)(d2 >> 6)*16384, y2 = (uint32_t)((d2 & 63)*2);
#pragma unroll
            for (int g = 0; g < 4; g++){
                int w = nw*32 + g*8 + 2*(l & 3);
                *(unsigned short*)(dsm + FXP + p1 + SWZ((uint32_t)(w*128)     + y1)) =
                    __half_as_ushort(__float2half(acc[f][g][0] + b1v));
                *(unsigned short*)(dsm + FXP + p1 + SWZ((uint32_t)((w+1)*128) + y1)) =
                    __half_as_ushort(__float2half(acc[f][g][1] + b1v));
                *(unsigned short*)(dsm + FXP + p2 + SWZ((uint32_t)(w*128)     + y2)) =
                    __half_as_ushort(__float2half(acc[f][g][2] + b2v));
                *(unsigned short*)(dsm + FXP + p2 + SWZ((uint32_t)((w+1)*128) + y2)) =
                    __half_as_ushort(__float2half(acc[f][g][3] + b2v));
            }
        }
    };

    // attention branch, fully smem-resident. Aoff holds x (A panels), Boff holds
    // partner (B panels). Sn overwrites Aoff; epilogue transposes through scratch.
    auto attn_branch = [&](uint32_t Aoff, uint32_t Boff, uint32_t scratch, int brIdx){
        zacc();
        gemm64f(sb, Aoff,         Boff,         l, mw, nw, acc);
        gemm64f(sb, Aoff + 16384, Boff + 16384, l, mw, nw, acc);
        float ls = 0.f, lq = 0.f;
#pragma unroll
        for (int f=0;f<4;f++)
#pragma unroll
            for (int g=0;g<4;g++)
#pragma unroll
                for (int e=0;e<4;e++){ ls += acc[f][g][e]; lq += acc[f][g][e]*acc[f][g][e]; }
        block_reduce_2(ls, lq, red);
        float mean = ls * (1.f/16384.f);
        float inv  = rsqrtf(lq * (1.f/16384.f) - mean*mean + EPSF);
#pragma unroll
        for (int f = 0; f < 4; f++){
            int c1 = mw*64 + f*16 + (l>>2), c2 = c1 + 8;
#pragma unroll
            for (int g = 0; g < 4; g++){
                int dd = nw*32 + g*8 + 2*(l & 3);
                uint32_t pn = (uint32_t)(dd >> 6)*16384;
                uint32_t byt = (uint32_t)((dd & 63)*2);
                *(unsigned*)(dsm + Aoff + pn + SWZ((uint32_t)(c1*128) + byt)) =
                    pack_f16((acc[f][g][0]-mean)*inv, (acc[f][g][1]-mean)*inv);
                *(unsigned*)(dsm + Aoff + pn + SWZ((uint32_t)(c2*128) + byt)) =
                    pack_f16((acc[f][g][2]-mean)*inv, (acc[f][g][3]-mean)*inv);
            }
        }
        __syncthreads();
        zacc();
        gemm64f(sb, Aoff,         FXP,         l, mw, nw, acc);
        gemm64f(sb, Aoff + 16384, FXP + 16384, l, mw, nw, acc);
        ls = 0.f; lq = 0.f;
#pragma unroll
        for (int f=0;f<4;f++)
#pragma unroll
            for (int g=0;g<4;g++)
#pragma unroll
                for (int e=0;e<4;e++){ ls += acc[f][g][e]; lq += acc[f][g][e]*acc[f][g][e]; }
        block_reduce_2(ls, lq, red);
        mean = ls * (1.f/16384.f);
        inv  = rsqrtf(lq * (1.f/16384.f) - mean*mean + EPSF);
        unsigned short* tile = (unsigned short*)(dsm + scratch);
#pragma unroll
        for (int f = 0; f < 4; f++){
            int c1 = mw*64 + f*16 + (l>>2), c2 = c1 + 8;
#pragma unroll
            for (int g = 0; g < 4; g++){
                int w = nw*32 + g*8 + 2*(l & 3);
                tile[(size_t)w*128 + c1]     = __half_as_ushort(__float2half((acc[f][g][0]-mean)*inv));
                tile[(size_t)(w+1)*128 + c1] = __half_as_ushort(__float2half((acc[f][g][1]-mean)*inv));
                tile[(size_t)w*128 + c2]     = __half_as_ushort(__float2half((acc[f][g][2]-mean)*inv));
                tile[(size_t)(w+1)*128 + c2] = __half_as_ushort(__float2half((acc[f][g][3]-mean)*inv));
            }
        }
        __syncthreads();
        const size_t rowb = (((size_t)b*130 + (h+1))*130 + 1)*384 + brIdx*128;
        for (int u = tid; u < 2048; u += 256){
            int w = u >> 4, j = u & 15;
            uint4 v = *(uint4*)(dsm + scratch + w*256 + j*16);
            *(uint4*)((char*)g_bhi + (rowb + (size_t)w*384)*2 + j*16) = v;
        }
        __syncthreads();
    };

    // ---------------- pipeline ----------------
    stage_x(0); stage_w(0, FW0); CP_COMMIT();      // C0
    stage_w(1, FW1); CP_COMMIT();                  // C1

    CP_WAIT1(); __syncthreads();                   // C0 done (X + Wx)
    conv_gemm(FW0); write_xp();
    __syncthreads();
    stage_w(2, FW0); CP_COMMIT();                  // C2

    CP_WAIT1(); __syncthreads();                   // C1 done (W1c)
    conv_gemm(FW1); write_Apanels(FX1, 1);
    __syncthreads();
    stage_w(3, FW1); CP_COMMIT();                  // C3

    CP_WAIT1(); __syncthreads();                   // C2 done (W2c)
    conv_gemm(FW0); write_Apanels(FX2, 2);
    __syncthreads();                               // XB free
    stage_x(1); CP_COMMIT();                       // C4 (xf slab)
    stage_w(4, FW0); CP_COMMIT();                  // C5 (Wr)

    CP_WAIT1(); __syncthreads();                   // C3+C4 done (Wf + xf)
    conv_gemm(FW1); write_Apanels(FXF, 3);
    __syncthreads();                               // XB free
    stage_x(2); CP_COMMIT();                       // C6 (xr slab) — overlaps branch 0

    attn_branch(FX1, FXF, FXF, 0);                 // pure smem

    CP_WAIT0(); __syncthreads();                   // C5+C6 done (Wr + xr)
    conv_gemm(FW0); write_Apanels(FX1, 4);         // xr -> X1 (free after branch 0)
    __syncthreads();

    attn_branch(FX2, FX1, FX1, 1);
}

// ============ conv3x3 weight prep: fp16 [tap][chunk][o][ci] =================
__global__ void presplit_kernel(const float* __restrict__ Wm)
{
    int idx = blockIdx.x*256 + threadIdx.x;
    if (idx >= 9*6*384*64) return;
    int ci = idx & 63;
    int o  = (idx >> 6) % 384;
    int r  = idx >> 6; r /= 384;
    int chunk = r % 6, tap = r / 6;
    float v = Wm[(size_t)o*3456 + (chunk*64 + ci)*9 + tap];
    g_wh[idx] = __half_as_ushort(__float2half(v));
}

// ====== conv3x3 fp16, PERSISTENT: 296 CTAs loop over 3072 tiles, 3-stage ring ======
#define OFF_AH 0
#define OFF_BH 16384
#define STAGE  33792
#define NTILE  3072
#define NCTA   296

__global__ __launch_bounds__(256, 2) void conv3x3_tc(
    const float* __restrict__ bm, const float* __restrict__ gamma,
    const float* __restrict__ beta, const float* __restrict__ rmean,
    const float* __restrict__ rvar, float* __restrict__ out)
{
    extern __shared__ char dsm[];
    const int tid = threadIdx.x, l = tid & 31, wid = tid >> 5;
    const int mw = wid & 1, nw = wid >> 1;
    const int bx = blockIdx.x;
    const uint32_t sb = smem_u32(dsm);

    const int nt = (NTILE - bx + NCTA - 1) / NCTA;
    const int total = nt * 54;

    auto stage = [&](int idx){
        int tile = bx + (idx / 54) * NCTA;
        int it = idx % 54;
        int ob = tile % 3; int r = tile / 3;
        int h = r & 127, b2 = r >> 7;
        int o0 = ob << 7;
        int tap = it/6, chunk = it - tap*6, kh = tap/3;
        uint32_t s0 = sb + (uint32_t)(idx % 3)*STAGE;
        const char* srcA = (const char*)g_wh + (((size_t)tap*6 + chunk)*384 + o0)*128;
        for (int u = tid; u < 1024; u += 256){
            CP16(s0 + OFF_AH + SWZ(u*16), srcA + u*16);
        }
        size_t rowbase = ((size_t)b2*130 + (h+kh))*130*768 + (size_t)chunk*128;
        const char* BH = (const char*)g_bhi;
        for (int u = tid; u < 1040; u += 256){
            int wp = u >> 3, j = u & 7;
            CP16(s0 + OFF_BH + SWZ(wp*128 + j*16), BH + rowbase + (size_t)wp*768 + j*16);
        }
    };

    float acc[4][4][4];

    stage(0); CP_COMMIT();
    int staged = 1;
    if (total > 1){ stage(1); CP_COMMIT(); staged = 2; }

    for (int i = 0; i < total; i++){
        if (staged - i - 1 >= 1) CP_WAIT1(); else CP_WAIT0();
        __syncthreads();

        const int tile = bx + (i / 54) * NCTA;
        const int it = i % 54;
        if (it == 0){
#pragma unroll
            for (int f=0;f<4;f++)
#pragma unroll
                for (int g=0;g<4;g++)
#pragma unroll
                    for (int e=0;e<4;e++) acc[f][g][e] = 0.f;
        }

        const int kw = (it/6) % 3;
        const uint32_t s0 = sb + (uint32_t)(i % 3)*STAGE;
#pragma unroll
        for (int ks = 0; ks < 4; ks++){
            uint32_t ah[4][4], bh[4][2];
            const uint32_t abyte = ks*32 + ((l>>4)<<4);
#pragma unroll
            for (int f = 0; f < 4; f++){
                int row = mw*64 + f*16 + (l & 15);
                uint32_t off = SWZ((uint32_t)(row*128) + abyte);
                LDSM4(ah[f][0],ah[f][1],ah[f][2],ah[f][3], s0 + OFF_AH + off);
            }
            const uint32_t bbyte = ks*32 + (((l>>3)&1)<<4);
#pragma unroll
            for (int g2 = 0; g2 < 2; g2++){
                int rowb = nw*32 + g2*16 + kw + (l & 7) + ((l>>4)<<3);
                uint32_t off = SWZ((uint32_t)(rowb*128) + bbyte);
                uint32_t t0,t1,t2,t3;
                LDSM4(t0,t1,t2,t3, s0 + OFF_BH + off);
                bh[g2*2][0]=t0; bh[g2*2][1]=t1; bh[g2*2+1][0]=t2; bh[g2*2+1][1]=t3;
            }
#pragma unroll
            for (int f = 0; f < 4; f++)
#pragma unroll
                for (int g = 0; g < 4; g++)
                    MMAF16(acc[f][g], ah[f], bh[g]);
        }

        if (staged < total){ stage(staged); CP_COMMIT(); staged++; }

        if (it == 53){
            int ob = tile % 3; int r = tile / 3;
            int h = r & 127, b2 = r >> 7;
            int o0 = ob << 7;
#pragma unroll
            for (int f = 0; f < 4; f++){
                int o1 = o0 + mw*64 + f*16 + (l >> 2);
                int o2 = o1 + 8;
                float sc1 = gamma[o1] * rsqrtf(rvar[o1] + EPSF);
                float sh1 = beta[o1] + (bm[o1] - rmean[o1]) * sc1;
                float sc2 = gamma[o2] * rsqrtf(rvar[o2] + EPSF);
                float sh2 = beta[o2] + (bm[o2] - rmean[o2]) * sc2;
                float* r1 = out + ((size_t)(b2*384 + o1))*HW + (size_t)h*128;
                float* r2 = out + ((size_t)(b2*384 + o2))*HW + (size_t)h*128;
#pragma unroll
                for (int g = 0; g < 4; g++){
                    int w = nw*32 + g*8 + 2*(l & 3);
                    float2 v1, v2;
                    v1.x = fmaxf(fmaf(acc[f][g][0], sc1, sh1), 0.f);
                    v1.y = fmaxf(fmaf(acc[f][g][1], sc1, sh1), 0.f);
                    v2.x = fmaxf(fmaf(acc[f][g][2], sc2, sh2), 0.f);
                    v2.y = fmaxf(fmaf(acc[f][g][3], sc2, sh2), 0.f);
                    *(float2*)(r1 + w) = v1;
                    *(float2*)(r2 + w) = v2;
                }
            }
        }
    }
}

// =============================================================================
extern "C" void kernel_launch(void* const* d_in, const int* in_sizes, int n_in,
                              void* d_out, int out_size)
{
    const float* x  = (const float*)d_in[0];
    const float* xf = (const float*)d_in[1];
    const float* xr = (const float*)d_in[2];
    const float* Wx = (const float*)d_in[3];
    const float* bx = (const float*)d_in[4];
    const float* W1 = (const float*)d_in[5];
    const float* b1 = (const float*)d_in[6];
    const float* W2 = (const float*)d_in[7];
    const float* b2 = (const float*)d_in[8];
    const float* Wf = (const float*)d_in[9];
    const float* bf = (const float*)d_in[10];
    const float* Wr = (const float*)d_in[11];
    const float* br_ = (const float*)d_in[12];
    const float* Wm = (const float*)d_in[13];
    const float* bm = (const float*)d_in[14];
    const float* gamma = (const float*)d_in[15];
    const float* beta  = (const float*)d_in[16];
    const float* rmean = (const float*)d_in[17];
    const float* rvar  = (const float*)d_in[18];
    float* out = (float*)d_out;

    cudaFuncSetAttribute(xpose_cvt,   cudaFuncAttributeMaxDynamicSharedMemorySize, 68096);
    cudaFuncSetAttribute(wcompose_kernel, cudaFuncAttributeMaxDynamicSharedMemorySize, 65536);
    cudaFuncSetAttribute(front_mma,   cudaFuncAttributeMaxDynamicSharedMemorySize, FSMEM);
    cudaFuncSetAttribute(conv3x3_tc,  cudaFuncAttributeMaxDynamicSharedMemorySize, 3*STAGE);

    xpose_cvt<<<dim3(3, 128, 8), 256, 68096>>>(x, xf, xr);
    wcompose_kernel<<<5, 256, 65536>>>(Wx, bx, W1, b1, W2, b2, Wf, bf, Wr, br_);
    wsplit_kernel<<<320, 256>>>();
    front_mma<<<dim3(128, 8), 256, FSMEM>>>();
    presplit_kernel<<<5184, 256>>>(Wm);
    conv3x3_tc<<<NCTA, 256, 3*STAGE>>>(bm, gamma, beta, rmean, rvar, out);
}

// round 14
// speedup vs baseline: 1.1773x; 1.0553x over previous
#include <cuda_runtime.h>
#include <cuda_bf16.h>
#include <cuda_fp16.h>
#include <cstdint>

#define EPSF 1e-5f
#define HW   16384
#define CHW  2097152

// ---------------- scratch (static device memory) ----------------
__device__ float g_wcf[5*16384];                        // composed 1x1 weights fp32
__device__ float g_bcf[5*128];                          // composed biases
__device__ __align__(16) unsigned short g_wsh[5*2*128*64];   // fp16 [which][pn][o][ci64]
__device__ __align__(16) unsigned short g_tih[3ull*8*CHW];   // fp16 inputs T: [inp][b][h][w][c]
__device__ unsigned short g_wh[9*6*384*64];             // conv3x3 W fp16: [tap][chunk][o][ci]
__device__ unsigned short g_bhi[8ull*130*130*384];      // conv3x3 in fp16: [b][hp][wp][ci]

// ---------------- helpers ----------------
__device__ __forceinline__ uint32_t smem_u32(const void* p){
    uint32_t a; asm("{ .reg .u64 t; cvta.to.shared.u64 t, %1; cvt.u32.u64 %0, t; }"
                    : "=r"(a) : "l"(p)); return a;
}
#define SWZ(x) ((x) ^ (((x)>>3)&0x70))
#define CP16(dst, src) asm volatile("cp.async.cg.shared.global [%0], [%1], 16;" \
    :: "r"((uint32_t)(dst)), "l"((const void*)(src)) : "memory")
#define CP_COMMIT() asm volatile("cp.async.commit_group;" ::: "memory")
#define CP_WAIT0()  asm volatile("cp.async.wait_group 0;" ::: "memory")
#define CP_WAIT1()  asm volatile("cp.async.wait_group 1;" ::: "memory")
#define CP_WAIT2()  asm volatile("cp.async.wait_group 2;" ::: "memory")
#define LDSM4(r0,r1,r2,r3,a) asm volatile( \
    "ldmatrix.sync.aligned.m8n8.x4.shared.b16 {%0,%1,%2,%3}, [%4];" \
    : "=r"(r0),"=r"(r1),"=r"(r2),"=r"(r3) : "r"(a))
#define MMAF16(c,a,b) asm volatile( \
    "mma.sync.aligned.m16n8k16.row.col.f32.f16.f16.f32 " \
    "{%0,%1,%2,%3},{%4,%5,%6,%7},{%8,%9},{%0,%1,%2,%3};" \
    : "+f"((c)[0]),"+f"((c)[1]),"+f"((c)[2]),"+f"((c)[3]) \
    : "r"((a)[0]),"r"((a)[1]),"r"((a)[2]),"r"((a)[3]), "r"((b)[0]),"r"((b)[1]))

__device__ __forceinline__ unsigned pack_f16(float v0, float v1){
    unsigned hp; asm("cvt.rn.f16x2.f32 %0, %1, %2;" : "=r"(hp) : "f"(v1), "f"(v0));
    return hp;
}

// 128x128x64 GEMM chunk, single-pass fp16 (256-thr kernels, warp grid 2x4).
__device__ __forceinline__ void gemm64f(uint32_t sb, uint32_t a0, uint32_t b0,
                                        int l, int mw, int nw, float acc[4][4][4])
{
#pragma unroll
    for (int ks = 0; ks < 4; ks++){
        uint32_t ah[4][4], bh[4][2];
        const uint32_t abyte = ks*32 + ((l>>4)<<4);
#pragma unroll
        for (int f = 0; f < 4; f++){
            int row = mw*64 + f*16 + (l & 15);
            uint32_t off = SWZ((uint32_t)(row*128) + abyte);
            LDSM4(ah[f][0],ah[f][1],ah[f][2],ah[f][3], sb + a0 + off);
        }
        const uint32_t bbyte = ks*32 + (((l>>3)&1)<<4);
#pragma unroll
        for (int g2 = 0; g2 < 2; g2++){
            int rowb = nw*32 + g2*16 + (l & 7) + ((l>>4)<<3);
            uint32_t off = SWZ((uint32_t)(rowb*128) + bbyte);
            uint32_t t0,t1,t2,t3;
            LDSM4(t0,t1,t2,t3, sb + b0 + off);
            bh[g2*2][0]=t0; bh[g2*2][1]=t1; bh[g2*2+1][0]=t2; bh[g2*2+1][1]=t3;
        }
#pragma unroll
        for (int f = 0; f < 4; f++)
#pragma unroll
            for (int g = 0; g < 4; g++)
                MMAF16(acc[f][g], ah[f], bh[g]);
    }
}

__device__ __forceinline__ void block_reduce_2(float& s, float& q, float* red)
{
#pragma unroll
    for (int off=16; off>0; off>>=1){
        s += __shfl_down_sync(0xffffffffu, s, off);
        q += __shfl_down_sync(0xffffffffu, q, off);
    }
    const int wid = threadIdx.x >> 5;
    if ((threadIdx.x & 31) == 0){ red[wid] = s; red[8+wid] = q; }
    __syncthreads();
    s = 0.f; q = 0.f;
#pragma unroll
    for (int i=0;i<8;i++){ s += red[i]; q += red[8+i]; }
    __syncthreads();
}

// ==== transpose+convert: [b][c][h][w] -> [inp][b][h][w][c] fp16; inp0 also -> g_bhi ====
__global__ __launch_bounds__(256) void xpose_cvt(const float* __restrict__ x,
    const float* __restrict__ xf, const float* __restrict__ xr)
{
    extern __shared__ float tl[];   // [128][133]
    const int inp = blockIdx.x, h = blockIdx.y, b = blockIdx.z;
    const float* src = inp==0 ? x : (inp==1 ? xf : xr);
    const int tid = threadIdx.x;
    const float* sp = src + (size_t)b*CHW + (size_t)h*128;
    for (int u = tid; u < 4096; u += 256){
        int c = u >> 5, q = u & 31;
        float4 v = *(const float4*)(sp + (size_t)c*HW + 4*q);
        float* d = tl + c*133 + 4*q;
        d[0]=v.x; d[1]=v.y; d[2]=v.z; d[3]=v.w;
    }
    __syncthreads();
    const size_t obase = ((size_t)inp*1024 + b*128 + h) * 16384;
    const size_t bbase = (((size_t)b*130 + (h+1))*130)*384;
    for (int u = tid; u < 4096; u += 256){
        int cg = u & 31, w = u >> 5;
        float v0 = tl[(4*cg+0)*133 + w], v1 = tl[(4*cg+1)*133 + w];
        float v2 = tl[(4*cg+2)*133 + w], v3 = tl[(4*cg+3)*133 + w];
        uint2 pv = make_uint2(pack_f16(v0, v1), pack_f16(v2, v3));
        *(uint2*)&g_tih[obase + (size_t)w*128 + 4*cg] = pv;
        if (inp == 0)
            *(uint2*)&g_bhi[bbase + (size_t)(w+1)*384 + 256 + 4*cg] = pv;
    }
}

// ============ compose 1x1 weights: which 0:Wx 1:W1@Wx 2:W2@Wx 3:Wf 4:Wr =====
__global__ __launch_bounds__(256) void wcompose_kernel(
    const float* __restrict__ Wx, const float* __restrict__ bx,
    const float* __restrict__ W1, const float* __restrict__ b1,
    const float* __restrict__ W2, const float* __restrict__ b2,
    const float* __restrict__ Wf, const float* __restrict__ bf,
    const float* __restrict__ Wr, const float* __restrict__ br_)
{
    extern __shared__ float S[];
    const int which = blockIdx.x, tid = threadIdx.x;
    if (which == 0 || which >= 3){
        const float* Ws = which==0 ? Wx : (which==3 ? Wf : Wr);
        const float* bs = which==0 ? bx : (which==3 ? bf : br_);
        for (int i = tid; i < 16384; i += 256) g_wcf[which*16384 + i] = Ws[i];
        if (tid < 128) g_bcf[which*128 + tid] = bs[tid];
        return;
    }
    const float* Wo = (which==1) ? W1 : W2;
    const float* bo = (which==1) ? b1 : b2;
    for (int i = tid; i < 16384; i += 256) S[i] = Wx[i];
    __syncthreads();
    int r = tid >> 1, c0 = (tid & 1) * 64;
    float acc[64];
#pragma unroll
    for (int j = 0; j < 64; j++) acc[j] = 0.f;
    for (int k = 0; k < 128; k++){
        float a = Wo[r*128 + k];
#pragma unroll
        for (int j = 0; j < 64; j++) acc[j] = fmaf(a, S[k*128 + c0 + j], acc[j]);
    }
    for (int j = 0; j < 64; j++) g_wcf[which*16384 + r*128 + c0 + j] = acc[j];
    if (tid < 128){
        float s = bo[tid];
        for (int k = 0; k < 128; k++) s = fmaf(Wo[tid*128 + k], bx[k], s);
        g_bcf[which*128 + tid] = s;
    }
}

// split composed weights to fp16 panels [which][pn][o][ci64]
__global__ void wsplit_kernel()
{
    int idx = blockIdx.x*256 + threadIdx.x;
    if (idx >= 81920) return;
    int ci = idx & 63, o = (idx >> 6) & 127, pn = (idx >> 13) & 1, which = idx >> 14;
    g_wsh[idx] = __half_as_ushort(__float2half(g_wcf[which*16384 + o*128 + pn*64 + ci]));
}

// ==== FUSED front end: one CTA per (b,h) does 5 conv GEMMs + both attn branches ====
#define FXB  0u
#define FW0  32768u
#define FW1  65536u
#define FXP  98304u
#define FX1  131072u
#define FX2  163840u
#define FXF  196608u
#define FSMEM 229376

__global__ __launch_bounds__(256) void front_mma(void)
{
    extern __shared__ char dsm[];
    __shared__ float red[16];
    const int tid = threadIdx.x, l = tid & 31, wid = tid >> 5;
    const int mw = wid & 1, nw = wid >> 1;
    const int h = blockIdx.x, b = blockIdx.y;
    const uint32_t sb = smem_u32(dsm);

    auto stage_w = [&](int which, uint32_t off){
        const char* wH = (const char*)g_wsh + which*32768;
        for (int u = tid; u < 2048; u += 256){
            uint32_t d = off + (uint32_t)(u >> 10)*16384 + SWZ((uint32_t)((u & 1023)*16));
            CP16(sb + d, wH + u*16);
        }
    };
    auto stage_x = [&](int inp){
        const char* tH = (const char*)g_tih + ((size_t)inp*1024 + b*128 + h)*32768;
        for (int u = tid; u < 2048; u += 256){
            int w = u >> 4, j = u & 15;
            int pn = j >> 3, jj = j & 7;
            CP16(sb + FXB + pn*16384 + SWZ((uint32_t)(w*128 + jj*16)),
                 tH + w*256 + pn*128 + jj*16);
        }
    };

    float acc[4][4][4];
    auto zacc = [&](){
#pragma unroll
        for (int f=0;f<4;f++)
#pragma unroll
            for (int g=0;g<4;g++)
#pragma unroll
                for (int e=0;e<4;e++) acc[f][g][e] = 0.f;
    };
    auto conv_gemm = [&](uint32_t woff){
        zacc();
        gemm64f(sb, woff,         FXB,         l, mw, nw, acc);
        gemm64f(sb, woff + 16384, FXB + 16384, l, mw, nw, acc);
    };
    auto write_Apanels = [&](uint32_t doff, int which){
#pragma unroll
        for (int f = 0; f < 4; f++){
            int c1 = mw*64 + f*16 + (l>>2), c2 = c1 + 8;
            float b1v = g_bcf[which*128 + c1], b2v = g_bcf[which*128 + c2];
#pragma unroll
            for (int g = 0; g < 4; g++){
                int w = nw*32 + g*8 + 2*(l & 3);
                uint32_t pn = (uint32_t)(w >> 6)*16384;
                uint32_t byt = (uint32_t)((w & 63)*2);
                *(unsigned*)(dsm + doff + pn + SWZ((uint32_t)(c1*128) + byt)) =
                    pack_f16(acc[f][g][0] + b1v, acc[f][g][1] + b1v);
                *(unsigned*)(dsm + doff + pn + SWZ((uint32_t)(c2*128) + byt)) =
                    pack_f16(acc[f][g][2] + b2v, acc[f][g][3] + b2v);
            }
        }
    };
    auto write_xp = [&](){
#pragma unroll
        for (int f = 0; f < 4; f++){
            int d1 = mw*64 + f*16 + (l>>2), d2 = d1 + 8;
            float b1v = g_bcf[d1], b2v = g_bcf[d2];
            uint32_t p1 = (uint32_t)(d1 >> 6)*16384, y1 = (uint32_t)((d1 & 63)*2);
            uint32_t p2 = (uint32_t)(d2 >> 6)*16384, y2 = (uint32_t)((d2 & 63)*2);
#pragma unroll
            for (int g = 0; g < 4; g++){
                int w = nw*32 + g*8 + 2*(l & 3);
                *(unsigned short*)(dsm + FXP + p1 + SWZ((uint32_t)(w*128)     + y1)) =
                    __half_as_ushort(__float2half(acc[f][g][0] + b1v));
                *(unsigned short*)(dsm + FXP + p1 + SWZ((uint32_t)((w+1)*128) + y1)) =
                    __half_as_ushort(__float2half(acc[f][g][1] + b1v));
                *(unsigned short*)(dsm + FXP + p2 + SWZ((uint32_t)(w*128)     + y2)) =
                    __half_as_ushort(__float2half(acc[f][g][2] + b2v));
                *(unsigned short*)(dsm + FXP + p2 + SWZ((uint32_t)((w+1)*128) + y2)) =
                    __half_as_ushort(__float2half(acc[f][g][3] + b2v));
            }
        }
    };

    auto attn_branch = [&](uint32_t Aoff, uint32_t Boff, uint32_t scratch, int brIdx){
        zacc();
        gemm64f(sb, Aoff,         Boff,         l, mw, nw, acc);
        gemm64f(sb, Aoff + 16384, Boff + 16384, l, mw, nw, acc);
        float ls = 0.f, lq = 0.f;
#pragma unroll
        for (int f=0;f<4;f++)
#pragma unroll
            for (int g=0;g<4;g++)
#pragma unroll
                for (int e=0;e<4;e++){ ls += acc[f][g][e]; lq += acc[f][g][e]*acc[f][g][e]; }
        block_reduce_2(ls, lq, red);
        float mean = ls * (1.f/16384.f);
        float inv  = rsqrtf(lq * (1.f/16384.f) - mean*mean + EPSF);
#pragma unroll
        for (int f = 0; f < 4; f++){
            int c1 = mw*64 + f*16 + (l>>2), c2 = c1 + 8;
#pragma unroll
            for (int g = 0; g < 4; g++){
                int dd = nw*32 + g*8 + 2*(l & 3);
                uint32_t pn = (uint32_t)(dd >> 6)*16384;
                uint32_t byt = (uint32_t)((dd & 63)*2);
                *(unsigned*)(dsm + Aoff + pn + SWZ((uint32_t)(c1*128) + byt)) =
                    pack_f16((acc[f][g][0]-mean)*inv, (acc[f][g][1]-mean)*inv);
                *(unsigned*)(dsm + Aoff + pn + SWZ((uint32_t)(c2*128) + byt)) =
                    pack_f16((acc[f][g][2]-mean)*inv, (acc[f][g][3]-mean)*inv);
            }
        }
        __syncthreads();
        zacc();
        gemm64f(sb, Aoff,         FXP,         l, mw, nw, acc);
        gemm64f(sb, Aoff + 16384, FXP + 16384, l, mw, nw, acc);
        ls = 0.f; lq = 0.f;
#pragma unroll
        for (int f=0;f<4;f++)
#pragma unroll
            for (int g=0;g<4;g++)
#pragma unroll
                for (int e=0;e<4;e++){ ls += acc[f][g][e]; lq += acc[f][g][e]*acc[f][g][e]; }
        block_reduce_2(ls, lq, red);
        mean = ls * (1.f/16384.f);
        inv  = rsqrtf(lq * (1.f/16384.f) - mean*mean + EPSF);
        unsigned short* tile = (unsigned short*)(dsm + scratch);
#pragma unroll
        for (int f = 0; f < 4; f++){
            int c1 = mw*64 + f*16 + (l>>2), c2 = c1 + 8;
#pragma unroll
            for (int g = 0; g < 4; g++){
                int w = nw*32 + g*8 + 2*(l & 3);
                tile[(size_t)w*128 + c1]     = __half_as_ushort(__float2half((acc[f][g][0]-mean)*inv));
                tile[(size_t)(w+1)*128 + c1] = __half_as_ushort(__float2half((acc[f][g][1]-mean)*inv));
                tile[(size_t)w*128 + c2]     = __half_as_ushort(__float2half((acc[f][g][2]-mean)*inv));
                tile[(size_t)(w+1)*128 + c2] = __half_as_ushort(__float2half((acc[f][g][3]-mean)*inv));
            }
        }
        __syncthreads();
        const size_t rowb = (((size_t)b*130 + (h+1))*130 + 1)*384 + brIdx*128;
        for (int u = tid; u < 2048; u += 256){
            int w = u >> 4, j = u & 15;
            uint4 v = *(uint4*)(dsm + scratch + w*256 + j*16);
            *(uint4*)((char*)g_bhi + (rowb + (size_t)w*384)*2 + j*16) = v;
        }
        __syncthreads();
    };

    stage_x(0); stage_w(0, FW0); CP_COMMIT();
    stage_w(1, FW1); CP_COMMIT();

    CP_WAIT1(); __syncthreads();
    conv_gemm(FW0); write_xp();
    __syncthreads();
    stage_w(2, FW0); CP_COMMIT();

    CP_WAIT1(); __syncthreads();
    conv_gemm(FW1); write_Apanels(FX1, 1);
    __syncthreads();
    stage_w(3, FW1); CP_COMMIT();

    CP_WAIT1(); __syncthreads();
    conv_gemm(FW0); write_Apanels(FX2, 2);
    __syncthreads();
    stage_x(1); CP_COMMIT();
    stage_w(4, FW0); CP_COMMIT();

    CP_WAIT1(); __syncthreads();
    conv_gemm(FW1); write_Apanels(FXF, 3);
    __syncthreads();
    stage_x(2); CP_COMMIT();

    attn_branch(FX1, FXF, FXF, 0);

    CP_WAIT0(); __syncthreads();
    conv_gemm(FW0); write_Apanels(FX1, 4);
    __syncthreads();

    attn_branch(FX2, FX1, FX1, 1);
}

// ============ conv3x3 weight prep: fp16 [tap][chunk][o][ci] =================
__global__ void presplit_kernel(const float* __restrict__ Wm)
{
    int idx = blockIdx.x*256 + threadIdx.x;
    if (idx >= 9*6*384*64) return;
    int ci = idx & 63;
    int o  = (idx >> 6) % 384;
    int r  = idx >> 6; r /= 384;
    int chunk = r % 6, tap = r / 6;
    float v = Wm[(size_t)o*3456 + (chunk*64 + ci)*9 + tap];
    g_wh[idx] = __half_as_ushort(__float2half(v));
}

// ====== conv3x3 fp16, PERSISTENT, 128 thr (warps 2x2, 64x64/warp), B reused over kw ======
// step i: outer s = (i%54)/3 -> (kh = s/6, chunk = s%6), inner kw = i%3.
// A ring: 4 x 16KB at 0..64K (slot i&3). B ring: 2 x 16640B at 64K (slot (i/3)&1).
#define STG_A  16384
#define STG_B  16640
#define OFFB   65536
#define SMEM3  98816
#define NTILE  3072
#define NCTA   296

__global__ __launch_bounds__(128, 2) void conv3x3_tc(
    const float* __restrict__ bm, const float* __restrict__ gamma,
    const float* __restrict__ beta, const float* __restrict__ rmean,
    const float* __restrict__ rvar, float* __restrict__ out)
{
    extern __shared__ char dsm[];
    const int tid = threadIdx.x, l = tid & 31, wid = tid >> 5;
    const int mw = wid & 1, nw = wid >> 1;
    const int bx = blockIdx.x;
    const uint32_t sb = smem_u32(dsm);

    const int nt = (NTILE - bx + NCTA - 1) / NCTA;
    const int total = nt * 54;

    auto stageA = [&](int idx){
        int tile = bx + (idx / 54) * NCTA;
        int j = idx % 54;
        int s = j / 3, kw_ = j % 3;
        int kh = s / 6, chunk = s - kh*6;
        int tap = kh*3 + kw_;
        int o0 = (tile % 3) << 7;
        uint32_t s0 = sb + (uint32_t)(idx & 3)*STG_A;
        const char* srcA = (const char*)g_wh + (((size_t)tap*6 + chunk)*384 + o0)*128;
        for (int u = tid; u < 1024; u += 128)
            CP16(s0 + SWZ(u*16), srcA + u*16);
    };
    auto stageB = [&](int idx){                 // only called when idx % 3 == 0
        int tile = bx + (idx / 54) * NCTA;
        int s = (idx % 54) / 3;
        int kh = s / 6, chunk = s - kh*6;
        int r = tile / 3;
        int h = r & 127, b2 = r >> 7;
        uint32_t s0 = sb + OFFB + (uint32_t)((idx/3) & 1)*STG_B;
        size_t rowbase = ((size_t)b2*130 + (h+kh))*130*768 + (size_t)chunk*128;
        const char* BH = (const char*)g_bhi;
        for (int u = tid; u < 1040; u += 128){
            int wp = u >> 3, jj = u & 7;
            CP16(s0 + SWZ(wp*128 + jj*16), BH + rowbase + (size_t)wp*768 + jj*16);
        }
    };

    float acc[4][8][4];

    stageA(0); stageB(0); CP_COMMIT();
    stageA(1); CP_COMMIT();
    stageA(2); CP_COMMIT();

    for (int i = 0; i < total; i++){
        const int rem = total - 1 - i;
        if (rem >= 2) CP_WAIT2(); else if (rem == 1) CP_WAIT1(); else CP_WAIT0();
        __syncthreads();

        const int j = i % 54;
        const int kw = j % 3;
        if (j == 0){
#pragma unroll
            for (int f=0;f<4;f++)
#pragma unroll
                for (int g=0;g<8;g++)
#pragma unroll
                    for (int e=0;e<4;e++) acc[f][g][e] = 0.f;
        }

        const uint32_t sA = sb + (uint32_t)(i & 3)*STG_A;
        const uint32_t sB = sb + OFFB + (uint32_t)((i/3) & 1)*STG_B;
#pragma unroll
        for (int ks = 0; ks < 4; ks++){
            uint32_t ah[4][4], bh[8][2];
            const uint32_t abyte = ks*32 + ((l>>4)<<4);
#pragma unroll
            for (int f = 0; f < 4; f++){
                int row = mw*64 + f*16 + (l & 15);
                uint32_t off = SWZ((uint32_t)(row*128) + abyte);
                LDSM4(ah[f][0],ah[f][1],ah[f][2],ah[f][3], sA + off);
            }
            const uint32_t bbyte = ks*32 + (((l>>3)&1)<<4);
#pragma unroll
            for (int g2 = 0; g2 < 4; g2++){
                int rowb = nw*64 + g2*16 + kw + (l & 7) + ((l>>4)<<3);
                uint32_t off = SWZ((uint32_t)(rowb*128) + bbyte);
                uint32_t t0,t1,t2,t3;
                LDSM4(t0,t1,t2,t3, sB + off);
                bh[g2*2][0]=t0; bh[g2*2][1]=t1; bh[g2*2+1][0]=t2; bh[g2*2+1][1]=t3;
            }
#pragma unroll
            for (int f = 0; f < 4; f++)
#pragma unroll
                for (int g = 0; g < 8; g++)
                    MMAF16(acc[f][g], ah[f], bh[g]);
        }

        if (i + 3 < total){
            stageA(i+3);
            if (((i+3) % 3) == 0) stageB(i+3);
            CP_COMMIT();
        }

        if (j == 53){
            int tile = bx + (i / 54) * NCTA;
            int o0 = (tile % 3) << 7;
            int r = tile / 3;
            int h = r & 127, b2 = r >> 7;
#pragma unroll
            for (int f = 0; f < 4; f++){
                int o1 = o0 + mw*64 + f*16 + (l >> 2);
                int o2 = o1 + 8;
                float sc1 = gamma[o1] * rsqrtf(rvar[o1] + EPSF);
                float sh1 = beta[o1] + (bm[o1] - rmean[o1]) * sc1;
                float sc2 = gamma[o2] * rsqrtf(rvar[o2] + EPSF);
                float sh2 = beta[o2] + (bm[o2] - rmean[o2]) * sc2;
                float* r1 = out + ((size_t)(b2*384 + o1))*HW + (size_t)h*128;
                float* r2 = out + ((size_t)(b2*384 + o2))*HW + (size_t)h*128;
#pragma unroll
                for (int g = 0; g < 8; g++){
                    int w = nw*64 + g*8 + 2*(l & 3);
                    float2 v1, v2;
                    v1.x = fmaxf(fmaf(acc[f][g][0], sc1, sh1), 0.f);
                    v1.y = fmaxf(fmaf(acc[f][g][1], sc1, sh1), 0.f);
                    v2.x = fmaxf(fmaf(acc[f][g][2], sc2, sh2), 0.f);
                    v2.y = fmaxf(fmaf(acc[f][g][3], sc2, sh2), 0.f);
                    *(float2*)(r1 + w) = v1;
                    *(float2*)(r2 + w) = v2;
                }
            }
        }
    }
}

// =============================================================================
extern "C" void kernel_launch(void* const* d_in, const int* in_sizes, int n_in,
                              void* d_out, int out_size)
{
    const float* x  = (const float*)d_in[0];
    const float* xf = (const float*)d_in[1];
    const float* xr = (const float*)d_in[2];
    const float* Wx = (const float*)d_in[3];
    const float* bx = (const float*)d_in[4];
    const float* W1 = (const float*)d_in[5];
    const float* b1 = (const float*)d_in[6];
    const float* W2 = (const float*)d_in[7];
    const float* b2 = (const float*)d_in[8];
    const float* Wf = (const float*)d_in[9];
    const float* bf = (const float*)d_in[10];
    const float* Wr = (const float*)d_in[11];
    const float* br_ = (const float*)d_in[12];
    const float* Wm = (const float*)d_in[13];
    const float* bm = (const float*)d_in[14];
    const float* gamma = (const float*)d_in[15];
    const float* beta  = (const float*)d_in[16];
    const float* rmean = (const float*)d_in[17];
    const float* rvar  = (const float*)d_in[18];
    float* out = (float*)d_out;

    cudaFuncSetAttribute(xpose_cvt,   cudaFuncAttributeMaxDynamicSharedMemorySize, 68096);
    cudaFuncSetAttribute(wcompose_kernel, cudaFuncAttributeMaxDynamicSharedMemorySize, 65536);
    cudaFuncSetAttribute(front_mma,   cudaFuncAttributeMaxDynamicSharedMemorySize, FSMEM);
    cudaFuncSetAttribute(conv3x3_tc,  cudaFuncAttributeMaxDynamicSharedMemorySize, SMEM3);

    xpose_cvt<<<dim3(3, 128, 8), 256, 68096>>>(x, xf, xr);
    wcompose_kernel<<<5, 256, 65536>>>(Wx, bx, W1, b1, W2, b2, Wf, bf, Wr, br_);
    wsplit_kernel<<<320, 256>>>();
    front_mma<<<dim3(128, 8), 256, FSMEM>>>();
    presplit_kernel<<<5184, 256>>>(Wm);
    conv3x3_tc<<<NCTA, 128, SMEM3>>>(bm, gamma, beta, rmean, rvar, out);
}

// round 15
// speedup vs baseline: 1.2026x; 1.0215x over previous
#include <cuda_runtime.h>
#include <cuda_bf16.h>
#include <cuda_fp16.h>
#include <cstdint>

#define EPSF 1e-5f
#define HW   16384
#define CHW  2097152

// ---------------- scratch (static device memory) ----------------
__device__ float g_wcf[5*16384];                        // composed 1x1 weights fp32
__device__ float g_bcf[5*128];                          // composed biases
__device__ __align__(16) unsigned short g_wsh[5*2*128*64];   // fp16 [which][pn][o][ci64]
__device__ __align__(16) unsigned short g_tih[3ull*8*CHW];   // fp16 inputs T: [inp][b][h][w][c]
__device__ unsigned short g_wh[9*6*384*64];             // conv3x3 W fp16: [tap][chunk][o][ci]
__device__ unsigned short g_bhi[8ull*130*130*384];      // conv3x3 in fp16: [b][hp][wp][ci]

// ---------------- helpers ----------------
__device__ __forceinline__ uint32_t smem_u32(const void* p){
    uint32_t a; asm("{ .reg .u64 t; cvta.to.shared.u64 t, %1; cvt.u32.u64 %0, t; }"
                    : "=r"(a) : "l"(p)); return a;
}
#define SWZ(x) ((x) ^ (((x)>>3)&0x70))
#define CP16(dst, src) asm volatile("cp.async.cg.shared.global [%0], [%1], 16;" \
    :: "r"((uint32_t)(dst)), "l"((const void*)(src)) : "memory")
#define CP_COMMIT() asm volatile("cp.async.commit_group;" ::: "memory")
#define CP_WAIT0()  asm volatile("cp.async.wait_group 0;" ::: "memory")
#define CP_WAIT1()  asm volatile("cp.async.wait_group 1;" ::: "memory")
#define CP_WAIT2()  asm volatile("cp.async.wait_group 2;" ::: "memory")
#define LDSM4(r0,r1,r2,r3,a) asm volatile( \
    "ldmatrix.sync.aligned.m8n8.x4.shared.b16 {%0,%1,%2,%3}, [%4];" \
    : "=r"(r0),"=r"(r1),"=r"(r2),"=r"(r3) : "r"(a))
#define MMAF16(c,a,b) asm volatile( \
    "mma.sync.aligned.m16n8k16.row.col.f32.f16.f16.f32 " \
    "{%0,%1,%2,%3},{%4,%5,%6,%7},{%8,%9},{%0,%1,%2,%3};" \
    : "+f"((c)[0]),"+f"((c)[1]),"+f"((c)[2]),"+f"((c)[3]) \
    : "r"((a)[0]),"r"((a)[1]),"r"((a)[2]),"r"((a)[3]), "r"((b)[0]),"r"((b)[1]))

__device__ __forceinline__ unsigned pack_f16(float v0, float v1){
    unsigned hp; asm("cvt.rn.f16x2.f32 %0, %1, %2;" : "=r"(hp) : "f"(v1), "f"(v0));
    return hp;
}

// 128x128x64 GEMM chunk, single-pass fp16, ks-pipelined fragment loads.
__device__ __forceinline__ void gemm64f(uint32_t sb, uint32_t a0, uint32_t b0,
                                        int l, int mw, int nw, float acc[4][4][4])
{
    uint32_t ah[2][4][4], bh[2][4][2];
    auto loadf = [&](int ks, int buf){
        const uint32_t abyte = (uint32_t)(ks*32) + ((l>>4)<<4);
#pragma unroll
        for (int f = 0; f < 4; f++){
            int row = mw*64 + f*16 + (l & 15);
            uint32_t off = SWZ((uint32_t)(row*128) + abyte);
            LDSM4(ah[buf][f][0],ah[buf][f][1],ah[buf][f][2],ah[buf][f][3], sb + a0 + off);
        }
        const uint32_t bbyte = (uint32_t)(ks*32) + (((l>>3)&1)<<4);
#pragma unroll
        for (int g2 = 0; g2 < 2; g2++){
            int rowb = nw*32 + g2*16 + (l & 7) + ((l>>4)<<3);
            uint32_t off = SWZ((uint32_t)(rowb*128) + bbyte);
            uint32_t t0,t1,t2,t3;
            LDSM4(t0,t1,t2,t3, sb + b0 + off);
            bh[buf][g2*2][0]=t0; bh[buf][g2*2][1]=t1;
            bh[buf][g2*2+1][0]=t2; bh[buf][g2*2+1][1]=t3;
        }
    };
    loadf(0, 0);
#pragma unroll
    for (int ks = 0; ks < 4; ks++){
        const int cur = ks & 1;
        if (ks < 3) loadf(ks+1, cur^1);
#pragma unroll
        for (int f = 0; f < 4; f++)
#pragma unroll
            for (int g = 0; g < 4; g++)
                MMAF16(acc[f][g], ah[cur][f], bh[cur][g]);
    }
}

__device__ __forceinline__ void block_reduce_2(float& s, float& q, float* red)
{
#pragma unroll
    for (int off=16; off>0; off>>=1){
        s += __shfl_down_sync(0xffffffffu, s, off);
        q += __shfl_down_sync(0xffffffffu, q, off);
    }
    const int wid = threadIdx.x >> 5;
    if ((threadIdx.x & 31) == 0){ red[wid] = s; red[8+wid] = q; }
    __syncthreads();
    s = 0.f; q = 0.f;
#pragma unroll
    for (int i=0;i<8;i++){ s += red[i]; q += red[8+i]; }
    __syncthreads();
}

// ==== transpose+convert: [b][c][h][w] -> [inp][b][h][w][c] fp16; inp0 also -> g_bhi ====
__global__ __launch_bounds__(256) void xpose_cvt(const float* __restrict__ x,
    const float* __restrict__ xf, const float* __restrict__ xr)
{
    extern __shared__ float tl[];   // [128][133]
    const int inp = blockIdx.x, h = blockIdx.y, b = blockIdx.z;
    const float* src = inp==0 ? x : (inp==1 ? xf : xr);
    const int tid = threadIdx.x;
    const float* sp = src + (size_t)b*CHW + (size_t)h*128;
    for (int u = tid; u < 4096; u += 256){
        int c = u >> 5, q = u & 31;
        float4 v = *(const float4*)(sp + (size_t)c*HW + 4*q);
        float* d = tl + c*133 + 4*q;
        d[0]=v.x; d[1]=v.y; d[2]=v.z; d[3]=v.w;
    }
    __syncthreads();
    const size_t obase = ((size_t)inp*1024 + b*128 + h) * 16384;
    const size_t bbase = (((size_t)b*130 + (h+1))*130)*384;
    for (int u = tid; u < 4096; u += 256){
        int cg = u & 31, w = u >> 5;
        float v0 = tl[(4*cg+0)*133 + w], v1 = tl[(4*cg+1)*133 + w];
        float v2 = tl[(4*cg+2)*133 + w], v3 = tl[(4*cg+3)*133 + w];
        uint2 pv = make_uint2(pack_f16(v0, v1), pack_f16(v2, v3));
        *(uint2*)&g_tih[obase + (size_t)w*128 + 4*cg] = pv;
        if (inp == 0)
            *(uint2*)&g_bhi[bbase + (size_t)(w+1)*384 + 256 + 4*cg] = pv;
    }
}

// ============ compose 1x1 weights: which 0:Wx 1:W1@Wx 2:W2@Wx 3:Wf 4:Wr =====
__global__ __launch_bounds__(256) void wcompose_kernel(
    const float* __restrict__ Wx, const float* __restrict__ bx,
    const float* __restrict__ W1, const float* __restrict__ b1,
    const float* __restrict__ W2, const float* __restrict__ b2,
    const float* __restrict__ Wf, const float* __restrict__ bf,
    const float* __restrict__ Wr, const float* __restrict__ br_)
{
    extern __shared__ float S[];
    const int which = blockIdx.x, tid = threadIdx.x;
    if (which == 0 || which >= 3){
        const float* Ws = which==0 ? Wx : (which==3 ? Wf : Wr);
        const float* bs = which==0 ? bx : (which==3 ? bf : br_);
        for (int i = tid; i < 16384; i += 256) g_wcf[which*16384 + i] = Ws[i];
        if (tid < 128) g_bcf[which*128 + tid] = bs[tid];
        return;
    }
    const float* Wo = (which==1) ? W1 : W2;
    const float* bo = (which==1) ? b1 : b2;
    for (int i = tid; i < 16384; i += 256) S[i] = Wx[i];
    __syncthreads();
    int r = tid >> 1, c0 = (tid & 1) * 64;
    float acc[64];
#pragma unroll
    for (int j = 0; j < 64; j++) acc[j] = 0.f;
    for (int k = 0; k < 128; k++){
        float a = Wo[r*128 + k];
#pragma unroll
        for (int j = 0; j < 64; j++) acc[j] = fmaf(a, S[k*128 + c0 + j], acc[j]);
    }
    for (int j = 0; j < 64; j++) g_wcf[which*16384 + r*128 + c0 + j] = acc[j];
    if (tid < 128){
        float s = bo[tid];
        for (int k = 0; k < 128; k++) s = fmaf(Wo[tid*128 + k], bx[k], s);
        g_bcf[which*128 + tid] = s;
    }
}

// split composed weights to fp16 panels [which][pn][o][ci64]
__global__ void wsplit_kernel()
{
    int idx = blockIdx.x*256 + threadIdx.x;
    if (idx >= 81920) return;
    int ci = idx & 63, o = (idx >> 6) & 127, pn = (idx >> 13) & 1, which = idx >> 14;
    g_wsh[idx] = __half_as_ushort(__float2half(g_wcf[which*16384 + o*128 + pn*64 + ci]));
}

// ==== FUSED front end: one CTA per (b,h) does 5 conv GEMMs + both attn branches ====
#define FXB  0u
#define FW0  32768u
#define FW1  65536u
#define FXP  98304u
#define FX1  131072u
#define FX2  163840u
#define FXF  196608u
#define FSMEM 229376

__global__ __launch_bounds__(256) void front_mma(void)
{
    extern __shared__ char dsm[];
    __shared__ float red[16];
    const int tid = threadIdx.x, l = tid & 31, wid = tid >> 5;
    const int mw = wid & 1, nw = wid >> 1;
    const int h = blockIdx.x, b = blockIdx.y;
    const uint32_t sb = smem_u32(dsm);

    auto stage_w = [&](int which, uint32_t off){
        const char* wH = (const char*)g_wsh + which*32768;
        for (int u = tid; u < 2048; u += 256){
            uint32_t d = off + (uint32_t)(u >> 10)*16384 + SWZ((uint32_t)((u & 1023)*16));
            CP16(sb + d, wH + u*16);
        }
    };
    auto stage_x = [&](int inp){
        const char* tH = (const char*)g_tih + ((size_t)inp*1024 + b*128 + h)*32768;
        for (int u = tid; u < 2048; u += 256){
            int w = u >> 4, j = u & 15;
            int pn = j >> 3, jj = j & 7;
            CP16(sb + FXB + pn*16384 + SWZ((uint32_t)(w*128 + jj*16)),
                 tH + w*256 + pn*128 + jj*16);
        }
    };

    float acc[4][4][4];
    auto zacc = [&](){
#pragma unroll
        for (int f=0;f<4;f++)
#pragma unroll
            for (int g=0;g<4;g++)
#pragma unroll
                for (int e=0;e<4;e++) acc[f][g][e] = 0.f;
    };
    auto conv_gemm = [&](uint32_t woff){
        zacc();
        gemm64f(sb, woff,         FXB,         l, mw, nw, acc);
        gemm64f(sb, woff + 16384, FXB + 16384, l, mw, nw, acc);
    };
    auto write_Apanels = [&](uint32_t doff, int which){
#pragma unroll
        for (int f = 0; f < 4; f++){
            int c1 = mw*64 + f*16 + (l>>2), c2 = c1 + 8;
            float b1v = g_bcf[which*128 + c1], b2v = g_bcf[which*128 + c2];
#pragma unroll
            for (int g = 0; g < 4; g++){
                int w = nw*32 + g*8 + 2*(l & 3);
                uint32_t pn = (uint32_t)(w >> 6)*16384;
                uint32_t byt = (uint32_t)((w & 63)*2);
                *(unsigned*)(dsm + doff + pn + SWZ((uint32_t)(c1*128) + byt)) =
                    pack_f16(acc[f][g][0] + b1v, acc[f][g][1] + b1v);
                *(unsigned*)(dsm + doff + pn + SWZ((uint32_t)(c2*128) + byt)) =
                    pack_f16(acc[f][g][2] + b2v, acc[f][g][3] + b2v);
            }
        }
    };
    auto write_xp = [&](){
#pragma unroll
        for (int f = 0; f < 4; f++){
            int d1 = mw*64 + f*16 + (l>>2), d2 = d1 + 8;
            float b1v = g_bcf[d1], b2v = g_bcf[d2];
            uint32_t p1 = (uint32_t)(d1 >> 6)*16384, y1 = (uint32_t)((d1 & 63)*2);
            uint32_t p2 = (uint32_t)(d2 >> 6)*16384, y2 = (uint32_t)((d2 & 63)*2);
#pragma unroll
            for (int g = 0; g < 4; g++){
                int w = nw*32 + g*8 + 2*(l & 3);
                *(unsigned short*)(dsm + FXP + p1 + SWZ((uint32_t)(w*128)     + y1)) =
                    __half_as_ushort(__float2half(acc[f][g][0] + b1v));
                *(unsigned short*)(dsm + FXP + p1 + SWZ((uint32_t)((w+1)*128) + y1)) =
                    __half_as_ushort(__float2half(acc[f][g][1] + b1v));
                *(unsigned short*)(dsm + FXP + p2 + SWZ((uint32_t)(w*128)     + y2)) =
                    __half_as_ushort(__float2half(acc[f][g][2] + b2v));
                *(unsigned short*)(dsm + FXP + p2 + SWZ((uint32_t)((w+1)*128) + y2)) =
                    __half_as_ushort(__float2half(acc[f][g][3] + b2v));
            }
        }
    };

    auto attn_branch = [&](uint32_t Aoff, uint32_t Boff, uint32_t scratch, int brIdx){
        zacc();
        gemm64f(sb, Aoff,         Boff,         l, mw, nw, acc);
        gemm64f(sb, Aoff + 16384, Boff + 16384, l, mw, nw, acc);
        float ls = 0.f, lq = 0.f;
#pragma unroll
        for (int f=0;f<4;f++)
#pragma unroll
            for (int g=0;g<4;g++)
#pragma unroll
                for (int e=0;e<4;e++){ ls += acc[f][g][e]; lq += acc[f][g][e]*acc[f][g][e]; }
        block_reduce_2(ls, lq, red);
        float mean = ls * (1.f/16384.f);
        float inv  = rsqrtf(lq * (1.f/16384.f) - mean*mean + EPSF);
#pragma unroll
        for (int f = 0; f < 4; f++){
            int c1 = mw*64 + f*16 + (l>>2), c2 = c1 + 8;
#pragma unroll
            for (int g = 0; g < 4; g++){
                int dd = nw*32 + g*8 + 2*(l & 3);
                uint32_t pn = (uint32_t)(dd >> 6)*16384;
                uint32_t byt = (uint32_t)((dd & 63)*2);
                *(unsigned*)(dsm + Aoff + pn + SWZ((uint32_t)(c1*128) + byt)) =
                    pack_f16((acc[f][g][0]-mean)*inv, (acc[f][g][1]-mean)*inv);
                *(unsigned*)(dsm + Aoff + pn + SWZ((uint32_t)(c2*128) + byt)) =
                    pack_f16((acc[f][g][2]-mean)*inv, (acc[f][g][3]-mean)*inv);
            }
        }
        __syncthreads();
        zacc();
        gemm64f(sb, Aoff,         FXP,         l, mw, nw, acc);
        gemm64f(sb, Aoff + 16384, FXP + 16384, l, mw, nw, acc);
        ls = 0.f; lq = 0.f;
#pragma unroll
        for (int f=0;f<4;f++)
#pragma unroll
            for (int g=0;g<4;g++)
#pragma unroll
                for (int e=0;e<4;e++){ ls += acc[f][g][e]; lq += acc[f][g][e]*acc[f][g][e]; }
        block_reduce_2(ls, lq, red);
        mean = ls * (1.f/16384.f);
        inv  = rsqrtf(lq * (1.f/16384.f) - mean*mean + EPSF);
        unsigned short* tile = (unsigned short*)(dsm + scratch);
#pragma unroll
        for (int f = 0; f < 4; f++){
            int c1 = mw*64 + f*16 + (l>>2), c2 = c1 + 8;
#pragma unroll
            for (int g = 0; g < 4; g++){
                int w = nw*32 + g*8 + 2*(l & 3);
                tile[(size_t)w*128 + c1]     = __half_as_ushort(__float2half((acc[f][g][0]-mean)*inv));
                tile[(size_t)(w+1)*128 + c1] = __half_as_ushort(__float2half((acc[f][g][1]-mean)*inv));
                tile[(size_t)w*128 + c2]     = __half_as_ushort(__float2half((acc[f][g][2]-mean)*inv));
                tile[(size_t)(w+1)*128 + c2] = __half_as_ushort(__float2half((acc[f][g][3]-mean)*inv));
            }
        }
        __syncthreads();
        const size_t rowb = (((size_t)b*130 + (h+1))*130 + 1)*384 + brIdx*128;
        for (int u = tid; u < 2048; u += 256){
            int w = u >> 4, j = u & 15;
            uint4 v = *(uint4*)(dsm + scratch + w*256 + j*16);
            *(uint4*)((char*)g_bhi + (rowb + (size_t)w*384)*2 + j*16) = v;
        }
        __syncthreads();
    };

    stage_x(0); stage_w(0, FW0); CP_COMMIT();
    stage_w(1, FW1); CP_COMMIT();

    CP_WAIT1(); __syncthreads();
    conv_gemm(FW0); write_xp();
    __syncthreads();
    stage_w(2, FW0); CP_COMMIT();

    CP_WAIT1(); __syncthreads();
    conv_gemm(FW1); write_Apanels(FX1, 1);
    __syncthreads();
    stage_w(3, FW1); CP_COMMIT();

    CP_WAIT1(); __syncthreads();
    conv_gemm(FW0); write_Apanels(FX2, 2);
    __syncthreads();
    stage_x(1); CP_COMMIT();
    stage_w(4, FW0); CP_COMMIT();

    CP_WAIT1(); __syncthreads();
    conv_gemm(FW1); write_Apanels(FXF, 3);
    __syncthreads();
    stage_x(2); CP_COMMIT();

    attn_branch(FX1, FXF, FXF, 0);

    CP_WAIT0(); __syncthreads();
    conv_gemm(FW0); write_Apanels(FX1, 4);
    __syncthreads();

    attn_branch(FX2, FX1, FX1, 1);
}

// ============ conv3x3 weight prep: fp16 [tap][chunk][o][ci] =================
__global__ void presplit_kernel(const float* __restrict__ Wm)
{
    int idx = blockIdx.x*256 + threadIdx.x;
    if (idx >= 9*6*384*64) return;
    int ci = idx & 63;
    int o  = (idx >> 6) % 384;
    int r  = idx >> 6; r /= 384;
    int chunk = r % 6, tap = r / 6;
    float v = Wm[(size_t)o*3456 + (chunk*64 + ci)*9 + tap];
    g_wh[idx] = __half_as_ushort(__float2half(v));
}

// ====== conv3x3 fp16, PERSISTENT, 128 thr (warps 2x2, 64x64/warp), B reused over kw ======
// step i: outer s = (i%54)/3 -> (kh = s/6, chunk = s%6), inner kw = i%3.
// A ring: 4 x 16KB (slot i&3). B ring: 2 x 16640B (slot (i/3)&1). ks-pipelined frags.
#define STG_A  16384
#define STG_B  16640
#define OFFB   65536
#define SMEM3  98816
#define NTILE  3072
#define NCTA   296

__global__ __launch_bounds__(128, 2) void conv3x3_tc(
    const float* __restrict__ bm, const float* __restrict__ gamma,
    const float* __restrict__ beta, const float* __restrict__ rmean,
    const float* __restrict__ rvar, float* __restrict__ out)
{
    extern __shared__ char dsm[];
    const int tid = threadIdx.x, l = tid & 31, wid = tid >> 5;
    const int mw = wid & 1, nw = wid >> 1;
    const int bx = blockIdx.x;
    const uint32_t sb = smem_u32(dsm);

    const int nt = (NTILE - bx + NCTA - 1) / NCTA;
    const int total = nt * 54;

    auto stageA = [&](int idx){
        int tile = bx + (idx / 54) * NCTA;
        int j = idx % 54;
        int s = j / 3, kw_ = j % 3;
        int kh = s / 6, chunk = s - kh*6;
        int tap = kh*3 + kw_;
        int o0 = (tile % 3) << 7;
        uint32_t s0 = sb + (uint32_t)(idx & 3)*STG_A;
        const char* srcA = (const char*)g_wh + (((size_t)tap*6 + chunk)*384 + o0)*128;
        for (int u = tid; u < 1024; u += 128)
            CP16(s0 + SWZ(u*16), srcA + u*16);
    };
    auto stageB = [&](int idx){                 // only called when idx % 3 == 0
        int tile = bx + (idx / 54) * NCTA;
        int s = (idx % 54) / 3;
        int kh = s / 6, chunk = s - kh*6;
        int r = tile / 3;
        int h = r & 127, b2 = r >> 7;
        uint32_t s0 = sb + OFFB + (uint32_t)((idx/3) & 1)*STG_B;
        size_t rowbase = ((size_t)b2*130 + (h+kh))*130*768 + (size_t)chunk*128;
        const char* BH = (const char*)g_bhi;
        for (int u = tid; u < 1040; u += 128){
            int wp = u >> 3, jj = u & 7;
            CP16(s0 + SWZ(wp*128 + jj*16), BH + rowbase + (size_t)wp*768 + jj*16);
        }
    };

    float acc[4][8][4];

    stageA(0); stageB(0); CP_COMMIT();
    stageA(1); CP_COMMIT();
    stageA(2); CP_COMMIT();

    for (int i = 0; i < total; i++){
        const int rem = total - 1 - i;
        if (rem >= 2) CP_WAIT2(); else if (rem == 1) CP_WAIT1(); else CP_WAIT0();
        __syncthreads();

        // issue next stage early so cp.async overlaps the MMA burst
        if (i + 3 < total){
            stageA(i+3);
            if (((i+3) % 3) == 0) stageB(i+3);
            CP_COMMIT();
        }

        const int j = i % 54;
        const int kw = j % 3;
        if (j == 0){
#pragma unroll
            for (int f=0;f<4;f++)
#pragma unroll
                for (int g=0;g<8;g++)
#pragma unroll
                    for (int e=0;e<4;e++) acc[f][g][e] = 0.f;
        }

        const uint32_t sA = sb + (uint32_t)(i & 3)*STG_A;
        const uint32_t sB = sb + OFFB + (uint32_t)((i/3) & 1)*STG_B;

        uint32_t ah[2][4][4], bh[2][8][2];
        auto load3 = [&](int ks, int buf){
            const uint32_t abyte = (uint32_t)(ks*32) + ((l>>4)<<4);
#pragma unroll
            for (int f = 0; f < 4; f++){
                int row = mw*64 + f*16 + (l & 15);
                uint32_t off = SWZ((uint32_t)(row*128) + abyte);
                LDSM4(ah[buf][f][0],ah[buf][f][1],ah[buf][f][2],ah[buf][f][3], sA + off);
            }
            const uint32_t bbyte = (uint32_t)(ks*32) + (((l>>3)&1)<<4);
#pragma unroll
            for (int g2 = 0; g2 < 4; g2++){
                int rowb = nw*64 + g2*16 + kw + (l & 7) + ((l>>4)<<3);
                uint32_t off = SWZ((uint32_t)(rowb*128) + bbyte);
                uint32_t t0,t1,t2,t3;
                LDSM4(t0,t1,t2,t3, sB + off);
                bh[buf][g2*2][0]=t0; bh[buf][g2*2][1]=t1;
                bh[buf][g2*2+1][0]=t2; bh[buf][g2*2+1][1]=t3;
            }
        };
        load3(0, 0);
#pragma unroll
        for (int ks = 0; ks < 4; ks++){
            const int cur = ks & 1;
            if (ks < 3) load3(ks+1, cur^1);
#pragma unroll
            for (int f = 0; f < 4; f++)
#pragma unroll
                for (int g = 0; g < 8; g++)
                    MMAF16(acc[f][g], ah[cur][f], bh[cur][g]);
        }

        if (j == 53){
            int tile = bx + (i / 54) * NCTA;
            int o0 = (tile % 3) << 7;
            int r = tile / 3;
            int h = r & 127, b2 = r >> 7;
#pragma unroll
            for (int f = 0; f < 4; f++){
                int o1 = o0 + mw*64 + f*16 + (l >> 2);
                int o2 = o1 + 8;
                float sc1 = gamma[o1] * rsqrtf(rvar[o1] + EPSF);
                float sh1 = beta[o1] + (bm[o1] - rmean[o1]) * sc1;
                float sc2 = gamma[o2] * rsqrtf(rvar[o2] + EPSF);
                float sh2 = beta[o2] + (bm[o2] - rmean[o2]) * sc2;
                float* r1 = out + ((size_t)(b2*384 + o1))*HW + (size_t)h*128;
                float* r2 = out + ((size_t)(b2*384 + o2))*HW + (size_t)h*128;
#pragma unroll
                for (int g = 0; g < 8; g++){
                    int w = nw*64 + g*8 + 2*(l & 3);
                    float2 v1, v2;
                    v1.x = fmaxf(fmaf(acc[f][g][0], sc1, sh1), 0.f);
                    v1.y = fmaxf(fmaf(acc[f][g][1], sc1, sh1), 0.f);
                    v2.x = fmaxf(fmaf(acc[f][g][2], sc2, sh2), 0.f);
                    v2.y = fmaxf(fmaf(acc[f][g][3], sc2, sh2), 0.f);
                    *(float2*)(r1 + w) = v1;
                    *(float2*)(r2 + w) = v2;
                }
            }
        }
    }
}

// =============================================================================
extern "C" void kernel_launch(void* const* d_in, const int* in_sizes, int n_in,
                              void* d_out, int out_size)
{
    const float* x  = (const float*)d_in[0];
    const float* xf = (const float*)d_in[1];
    const float* xr = (const float*)d_in[2];
    const float* Wx = (const float*)d_in[3];
    const float* bx = (const float*)d_in[4];
    const float* W1 = (const float*)d_in[5];
    const float* b1 = (const float*)d_in[6];
    const float* W2 = (const float*)d_in[7];
    const float* b2 = (const float*)d_in[8];
    const float* Wf = (const float*)d_in[9];
    const float* bf = (const float*)d_in[10];
    const float* Wr = (const float*)d_in[11];
    const float* br_ = (const float*)d_in[12];
    const float* Wm = (const float*)d_in[13];
    const float* bm = (const float*)d_in[14];
    const float* gamma = (const float*)d_in[15];
    const float* beta  = (const float*)d_in[16];
    const float* rmean = (const float*)d_in[17];
    const float* rvar  = (const float*)d_in[18];
    float* out = (float*)d_out;

    cudaFuncSetAttribute(xpose_cvt,   cudaFuncAttributeMaxDynamicSharedMemorySize, 68096);
    cudaFuncSetAttribute(wcompose_kernel, cudaFuncAttributeMaxDynamicSharedMemorySize, 65536);
    cudaFuncSetAttribute(front_mma,   cudaFuncAttributeMaxDynamicSharedMemorySize, FSMEM);
    cudaFuncSetAttribute(conv3x3_tc,  cudaFuncAttributeMaxDynamicSharedMemorySize, SMEM3);

    xpose_cvt<<<dim3(3, 128, 8), 256, 68096>>>(x, xf, xr);
    wcompose_kernel<<<5, 256, 65536>>>(Wx, bx, W1, b1, W2, b2, Wf, bf, Wr, br_);
    wsplit_kernel<<<320, 256>>>();
    front_mma<<<dim3(128, 8), 256, FSMEM>>>();
    presplit_kernel<<<5184, 256>>>(Wm);
    conv3x3_tc<<<NCTA, 128, SMEM3>>>(bm, gamma, beta, rmean, rvar, out);
}